// round 6
// baseline (speedup 1.0000x reference)
#include <cuda_runtime.h>
#include <cuda_fp16.h>
#include <cstdint>
#include <cstddef>

// Problem constants
#define BATCH 4
#define NPTS  16384
#define SPTS  4096
#define CF    128
#define CC    256
#define CIN   384
#define CMID  192
#define COUT  128
#define GROUPS 8
#define EPS_GN 1e-5f
#define EPS_D  1e-8f
#define BN_TOTAL (BATCH * NPTS)   // 65536
#define CTAS_PER_BATCH 128

// -------------------- scratch (device globals; no allocation) --------------------
__device__ __align__(16) __half g_comb_hi[(size_t)BN_TOTAL * CIN];
__device__ __align__(16) __half g_comb_lo[(size_t)BN_TOTAL * CIN];
__device__ __align__(16) float  g_h1[(size_t)BN_TOTAL * CMID];
__device__ int   g_idx[(size_t)BN_TOTAL * 3];
__device__ float g_wt[(size_t)BN_TOTAL * 3];
__device__ __align__(16) __half g_w1h[CMID * CIN], g_w1l[CMID * CIN];
__device__ __align__(16) __half g_w2h[COUT * CMID], g_w2l[COUT * CMID];
__device__ float g_part1[2 * 32 * CTAS_PER_BATCH];
__device__ float g_part2[2 * 32 * CTAS_PER_BATCH];
__device__ float g_a1[BATCH * CMID], g_b1[BATCH * CMID];
__device__ float g_a2[BATCH * COUT], g_b2[BATCH * COUT];

// ==================== helpers ====================
__device__ __forceinline__ uint32_t smem_u32(const void* p) {
    uint32_t a;
    asm("{ .reg .u64 t; cvta.to.shared.u64 t, %1; cvt.u32.u64 %0, t; }" : "=r"(a) : "l"(p));
    return a;
}
#define LDSM4(r0, r1, r2, r3, addr) \
    asm volatile("ldmatrix.sync.aligned.m8n8.x4.shared.b16 {%0,%1,%2,%3}, [%4];" \
        : "=r"(r0), "=r"(r1), "=r"(r2), "=r"(r3) : "r"(addr))
#define MMA16816(d, a0, a1, a2, a3, b0, b1) \
    asm volatile("mma.sync.aligned.m16n8k16.row.col.f32.f16.f16.f32 " \
        "{%0,%1,%2,%3},{%4,%5,%6,%7},{%8,%9},{%0,%1,%2,%3};" \
        : "+f"((d)[0]), "+f"((d)[1]), "+f"((d)[2]), "+f"((d)[3]) \
        : "r"(a0), "r"(a1), "r"(a2), "r"(a3), "r"(b0), "r"(b1))
#define CP16(dst, src) \
    asm volatile("cp.async.cg.shared.global [%0], [%1], 16;" :: "r"(dst), "l"(src))
#define CP_COMMIT() asm volatile("cp.async.commit_group;" ::: "memory")
#define CP_WAIT1()  asm volatile("cp.async.wait_group 1;" ::: "memory")

__device__ __forceinline__ void split2(float x, float y, uint32_t& h, uint32_t& l) {
    __half hx = __float2half_rn(x), hy = __float2half_rn(y);
    __half lx = __float2half_rn(x - __half2float(hx));
    __half ly = __float2half_rn(y - __half2float(hy));
    h = ((uint32_t)__half_as_ushort(hy) << 16) | __half_as_ushort(hx);
    l = ((uint32_t)__half_as_ushort(ly) << 16) | __half_as_ushort(lx);
}

// ==================== Kernel 1: kNN (K=3) + IDW, 2 queries/thread ====================
#define KNN_CHUNK 2048
__global__ void __launch_bounds__(128) knn_kernel(
    const float* __restrict__ fxyz, const float* __restrict__ cxyz,
    int* __restrict__ oidx, float* __restrict__ owt)
{
    __shared__ float4 cs[KNN_CHUNK];
    const int b = blockIdx.y;
    const int n0 = blockIdx.x * 256 + threadIdx.x;    // queries n0 and n0+128

    float qx[2], qy[2], qz[2], qn[2];
    float s0[2], s1[2], s2[2];
    int   i0[2], i1[2], i2[2];
    #pragma unroll
    for (int u = 0; u < 2; u++) {
        const float* fp = fxyz + ((size_t)b * NPTS + n0 + u * 128) * 3;
        qx[u] = fp[0]; qy[u] = fp[1]; qz[u] = fp[2];
        qn[u] = qx[u]*qx[u] + qy[u]*qy[u] + qz[u]*qz[u];
        s0[u] = s1[u] = s2[u] = 3.4e38f;
        i0[u] = i1[u] = i2[u] = 0;
    }

    for (int c0 = 0; c0 < SPTS; c0 += KNN_CHUNK) {
        __syncthreads();
        for (int j = threadIdx.x; j < KNN_CHUNK; j += 128) {
            const float* cp = cxyz + ((size_t)b * SPTS + c0 + j) * 3;
            float x = cp[0], y = cp[1], z = cp[2];
            cs[j] = make_float4(x, y, z, x*x + y*y + z*z);
        }
        __syncthreads();
        #pragma unroll 4
        for (int j = 0; j < KNN_CHUNK; j++) {
            float4 c = cs[j];
            #pragma unroll
            for (int u = 0; u < 2; u++) {
                float dot = qx[u]*c.x + qy[u]*c.y + qz[u]*c.z;
                float score = fmaf(-2.0f, dot, qn[u] + c.w);   // reference formula
                if (score < s2[u]) {
                    int idx = c0 + j;
                    if (score < s1[u]) {
                        s2[u] = s1[u]; i2[u] = i1[u];
                        if (score < s0[u]) { s1[u] = s0[u]; i1[u] = i0[u]; s0[u] = score; i0[u] = idx; }
                        else               { s1[u] = score; i1[u] = idx; }
                    } else { s2[u] = score; i2[u] = idx; }
                }
            }
        }
    }
    #pragma unroll
    for (int u = 0; u < 2; u++) {
        int ii[3] = { i0[u], i1[u], i2[u] };
        float w[3], wsum = 0.0f;
        #pragma unroll
        for (int k = 0; k < 3; k++) {
            const float* cp = cxyz + ((size_t)b * SPTS + ii[k]) * 3;
            float dx = qx[u] - cp[0], dy = qy[u] - cp[1], dz = qz[u] - cp[2];
            float d2 = fmaxf(dx*dx + dy*dy + dz*dz, EPS_D);
            w[k] = 1.0f / d2; wsum += w[k];
        }
        float inv = 1.0f / wsum;
        size_t base = ((size_t)b * NPTS + n0 + u * 128) * 3;
        #pragma unroll
        for (int k = 0; k < 3; k++) { oidx[base + k] = ii[k]; owt[base + k] = w[k] * inv; }
    }
}

// ==================== Kernel 2: weights fp32 -> fp16 hi/lo ====================
__global__ void prep_weights(const float* __restrict__ w1, const float* __restrict__ w2,
                             __half* w1h, __half* w1l, __half* w2h, __half* w2l)
{
    int i = blockIdx.x * 256 + threadIdx.x;
    if (i < CMID * CIN) {
        float x = w1[i];
        __half h = __float2half_rn(x);
        w1h[i] = h; w1l[i] = __float2half_rn(x - __half2float(h));
    }
    int j = i - CMID * CIN;
    if (j >= 0 && j < COUT * CMID) {
        float x = w2[j];
        __half h = __float2half_rn(x);
        w2h[j] = h; w2l[j] = __float2half_rn(x - __half2float(h));
    }
}

// ==================== Kernel 3: interp + concat -> fp16 hi/lo ====================
__global__ void __launch_bounds__(256) interp_kernel(
    const float* __restrict__ ffeat, const float* __restrict__ cfeat,
    const int* __restrict__ idx, const float* __restrict__ wt,
    __half* __restrict__ chi, __half* __restrict__ clo)
{
    const int gwarp = (blockIdx.x * 256 + threadIdx.x) >> 5;
    const int lane  = threadIdx.x & 31;
    const size_t p  = (size_t)gwarp;
    const int b     = (int)(p >> 14);

    const int*   ip = idx + p * 3;
    const float* wp = wt  + p * 3;
    int   j0 = ip[0], j1 = ip[1], j2 = ip[2];
    float w0 = wp[0], w1v = wp[1], w2v = wp[2];

    char* hbase = (char*)(chi + p * CIN);
    char* lbase = (char*)(clo + p * CIN);
    const float4* f4 = (const float4*)(ffeat + p * CF);
    {
        float4 v = f4[lane];
        uint32_t h0, l0, h1, l1;
        split2(v.x, v.y, h0, l0); split2(v.z, v.w, h1, l1);
        *(uint2*)(hbase + lane * 8) = make_uint2(h0, h1);
        *(uint2*)(lbase + lane * 8) = make_uint2(l0, l1);
    }
    const float4* c0 = (const float4*)(cfeat + ((size_t)b * SPTS + j0) * CC);
    const float4* c1 = (const float4*)(cfeat + ((size_t)b * SPTS + j1) * CC);
    const float4* c2 = (const float4*)(cfeat + ((size_t)b * SPTS + j2) * CC);
    #pragma unroll
    for (int t = 0; t < 2; t++) {
        int c = t * 32 + lane;
        float4 A = c0[c], B = c1[c], Cv = c2[c];
        float4 r;
        r.x = w0*A.x + w1v*B.x + w2v*Cv.x;
        r.y = w0*A.y + w1v*B.y + w2v*Cv.y;
        r.z = w0*A.z + w1v*B.z + w2v*Cv.z;
        r.w = w0*A.w + w1v*B.w + w2v*Cv.w;
        uint32_t h0, l0, h1, l1;
        split2(r.x, r.y, h0, l0); split2(r.z, r.w, h1, l1);
        *(uint2*)(hbase + 256 + c * 8) = make_uint2(h0, h1);
        *(uint2*)(lbase + 256 + c * 8) = make_uint2(l0, l1);
    }
}

// ==================== GEMM1: cp.async 3-stage + mma fp16x3 + fused GN1 stats ====================
// CTA 128x192, warps 2x4 (64x48), BK=32, stage = 51200 B, 3 stages
#define G1_STAGE 51200
#define G1_AH 0
#define G1_AL 10240
#define G1_BH 20480
#define G1_BL 35840
#define G1_SMEM (3 * G1_STAGE)   // 153600

__global__ void __launch_bounds__(256) gemm1_mma(
    const __half* __restrict__ Ah, const __half* __restrict__ Al,
    const __half* __restrict__ Bh, const __half* __restrict__ Bl,
    float* __restrict__ C, float* __restrict__ part)
{
    extern __shared__ char smem[];
    const uint32_t sb = smem_u32(smem);
    const int tid = threadIdx.x, lane = tid & 31, wid = tid >> 5;
    const int wm = wid & 1, wn = wid >> 1;
    const int m0 = blockIdx.x * 128;

    auto issue = [&](int it, int buf) {
        const int kc0 = it * 32;
        const uint32_t base = sb + buf * G1_STAGE;
        #pragma unroll
        for (int u = 0; u < 2; u++) {
            int i = u * 256 + tid;
            int row = i >> 2, ko = (i & 3) * 8;
            uint32_t d = base + row * 80 + ko * 2;
            CP16(d + G1_AH, Ah + (size_t)(m0 + row) * CIN + kc0 + ko);
            CP16(d + G1_AL, Al + (size_t)(m0 + row) * CIN + kc0 + ko);
        }
        #pragma unroll
        for (int q = 0; q < 3; q++) {
            int i = q * 256 + tid;
            int row = i >> 2, ko = (i & 3) * 8;
            uint32_t d = base + row * 80 + ko * 2;
            CP16(d + G1_BH, Bh + (size_t)row * CIN + kc0 + ko);
            CP16(d + G1_BL, Bl + (size_t)row * CIN + kc0 + ko);
        }
    };

    float acc[4][6][4];
    #pragma unroll
    for (int i = 0; i < 4; i++)
        #pragma unroll
        for (int j = 0; j < 6; j++)
            #pragma unroll
            for (int k = 0; k < 4; k++) acc[i][j][k] = 0.0f;

    issue(0, 0); CP_COMMIT();
    issue(1, 1); CP_COMMIT();

    const int lrow = lane & 15, lk = (lane >> 4) * 8;
    for (int it = 0; it < 12; it++) {
        CP_WAIT1();
        __syncthreads();
        if (it + 2 < 12) issue(it + 2, (it + 2) % 3);
        CP_COMMIT();                      // empty group when no issue: keeps count
        const uint32_t bufb = sb + (it % 3) * G1_STAGE;
        #pragma unroll
        for (int s = 0; s < 2; s++) {
            const int kc = s * 16;
            uint32_t fAh[4][4], fAl[4][4];
            #pragma unroll
            for (int mf = 0; mf < 4; mf++) {
                uint32_t off = (uint32_t)(((wm * 64 + mf * 16 + lrow) * 40 + kc + lk) * 2);
                LDSM4(fAh[mf][0], fAh[mf][1], fAh[mf][2], fAh[mf][3], bufb + G1_AH + off);
                LDSM4(fAl[mf][0], fAl[mf][1], fAl[mf][2], fAl[mf][3], bufb + G1_AL + off);
            }
            uint32_t fBh[6][2], fBl[6][2];
            #pragma unroll
            for (int q = 0; q < 3; q++) {
                uint32_t off = (uint32_t)(((wn * 48 + q * 16 + lrow) * 40 + kc + lk) * 2);
                uint32_t r0, r1, r2, r3;
                LDSM4(r0, r1, r2, r3, bufb + G1_BH + off);
                fBh[q*2][0] = r0; fBh[q*2][1] = r2;
                fBh[q*2+1][0] = r1; fBh[q*2+1][1] = r3;
                LDSM4(r0, r1, r2, r3, bufb + G1_BL + off);
                fBl[q*2][0] = r0; fBl[q*2][1] = r2;
                fBl[q*2+1][0] = r1; fBl[q*2+1][1] = r3;
            }
            #pragma unroll
            for (int mf = 0; mf < 4; mf++)
                #pragma unroll
                for (int nf = 0; nf < 6; nf++) {
                    MMA16816(acc[mf][nf], fAh[mf][0], fAh[mf][1], fAh[mf][2], fAh[mf][3],
                             fBh[nf][0], fBh[nf][1]);
                    MMA16816(acc[mf][nf], fAh[mf][0], fAh[mf][1], fAh[mf][2], fAh[mf][3],
                             fBl[nf][0], fBl[nf][1]);
                    MMA16816(acc[mf][nf], fAl[mf][0], fAl[mf][1], fAl[mf][2], fAl[mf][3],
                             fBh[nf][0], fBh[nf][1]);
                }
        }
        __syncthreads();
    }

    // epilogue: write C + GN1 partial stats
    const int g = lane >> 2, tig = lane & 3;
    float gs[16];
    #pragma unroll
    for (int i = 0; i < 16; i++) gs[i] = 0.0f;
    #pragma unroll
    for (int mf = 0; mf < 4; mf++)
        #pragma unroll
        for (int nf = 0; nf < 6; nf++) {
            int row = m0 + wm * 64 + mf * 16 + g;
            int col = wn * 48 + nf * 8 + tig * 2;
            float d0 = acc[mf][nf][0], d1 = acc[mf][nf][1];
            float d2 = acc[mf][nf][2], d3 = acc[mf][nf][3];
            *(float2*)(C + (size_t)row * CMID + col)       = make_float2(d0, d1);
            *(float2*)(C + (size_t)(row + 8) * CMID + col) = make_float2(d2, d3);
            int grp = col / 24;
            gs[grp]     += d0 + d1 + d2 + d3;
            gs[8 + grp] += d0*d0 + d1*d1 + d2*d2 + d3*d3;
        }
    __syncthreads();
    float* red = (float*)smem;
    #pragma unroll
    for (int i = 0; i < 16; i++) red[i * 256 + tid] = gs[i];
    __syncthreads();
    for (int off = 128; off > 0; off >>= 1) {
        if (tid < off) {
            #pragma unroll
            for (int i = 0; i < 16; i++) red[i * 256 + tid] += red[i * 256 + tid + off];
        }
        __syncthreads();
    }
    if (tid < 16) {
        int b = blockIdx.x >> 7, cta = blockIdx.x & 127;
        int grp = tid & 7;
        part[(tid >= 8 ? 4096 : 0) + (b * 8 + grp) * 128 + cta] = red[tid * 256];
    }
}

// ==================== GEMM2: cp.async 3-stage, GN1 affine+relu fused, GN2 stats ====================
// CTA 128x128, warps 2x4 (64x32), BK=32
// stage = A32 (128x40 fp32 = 20480) + BH 10240 + BL 10240 = 40960; conv AH/AL after stages
#define G2_STAGE 40960
#define G2_A32 0
#define G2_BH 20480
#define G2_BL 30720
#define G2_CAH (3 * G2_STAGE)            // 122880
#define G2_CAL (G2_CAH + 10240)          // 133120
#define G2_AFF (G2_CAL + 10240)          // 143360
#define G2_SMEM (G2_AFF + 2 * CMID * 4)  // 144896

__global__ void __launch_bounds__(256) gemm2_mma(
    const float* __restrict__ H,
    const __half* __restrict__ Bh, const __half* __restrict__ Bl,
    const float* __restrict__ a1, const float* __restrict__ b1,
    float* __restrict__ Out, float* __restrict__ part)
{
    extern __shared__ char smem[];
    const uint32_t sb = smem_u32(smem);
    const int tid = threadIdx.x, lane = tid & 31, wid = tid >> 5;
    const int wm = wid & 1, wn = wid >> 1;
    const int m0 = blockIdx.x * 128;
    const int bb = blockIdx.x >> 7;

    float* s_a = (float*)(smem + G2_AFF);
    float* s_b = s_a + CMID;
    for (int i = tid; i < CMID; i += 256) { s_a[i] = a1[bb * CMID + i]; s_b[i] = b1[bb * CMID + i]; }

    auto issue = [&](int it, int buf) {
        const int kc0 = it * 32;
        const uint32_t base = sb + buf * G2_STAGE;
        #pragma unroll
        for (int u = 0; u < 4; u++) {      // A32: 1024 x 16B ops
            int i = u * 256 + tid;
            int row = i >> 3, ko = (i & 7) * 4;
            CP16(base + G2_A32 + row * 160 + ko * 4, H + (size_t)(m0 + row) * CMID + kc0 + ko);
        }
        #pragma unroll
        for (int u = 0; u < 2; u++) {      // B hi/lo: 512 ops each
            int i = u * 256 + tid;
            int row = i >> 2, ko = (i & 3) * 8;
            uint32_t d = base + row * 80 + ko * 2;
            CP16(d + G2_BH, Bh + (size_t)row * CMID + kc0 + ko);
            CP16(d + G2_BL, Bl + (size_t)row * CMID + kc0 + ko);
        }
    };

    float acc[4][4][4];
    #pragma unroll
    for (int i = 0; i < 4; i++)
        #pragma unroll
        for (int j = 0; j < 4; j++)
            #pragma unroll
            for (int k = 0; k < 4; k++) acc[i][j][k] = 0.0f;

    __syncthreads();   // affine coefs visible
    issue(0, 0); CP_COMMIT();
    issue(1, 1); CP_COMMIT();

    const int crow = tid >> 1, cko = (tid & 1) * 16;
    const int lrow = lane & 15, lk = (lane >> 4) * 8;
    for (int it = 0; it < 6; it++) {
        CP_WAIT1();
        __syncthreads();
        if (it + 2 < 6) issue(it + 2, (it + 2) % 3);
        CP_COMMIT();
        const uint32_t bufb = sb + (it % 3) * G2_STAGE;
        // convert: fp32 + GN1 affine + relu -> hi/lo in convert buffer
        {
            const int kc0 = it * 32;
            const float* a32 = (const float*)(smem + (it % 3) * G2_STAGE + G2_A32);
            const float* rowp = a32 + crow * 40 + cko;
            uint32_t hq[8], lq[8];
            #pragma unroll
            for (int e = 0; e < 8; e++) {
                int c = kc0 + cko + e * 2;
                float x = fmaxf(fmaf(rowp[e*2],   s_a[c],   s_b[c]),   0.0f);
                float y = fmaxf(fmaf(rowp[e*2+1], s_a[c+1], s_b[c+1]), 0.0f);
                split2(x, y, hq[e], lq[e]);
            }
            uint32_t d = crow * 80 + cko * 2;
            *(uint4*)(smem + G2_CAH + d)      = make_uint4(hq[0], hq[1], hq[2], hq[3]);
            *(uint4*)(smem + G2_CAH + d + 16) = make_uint4(hq[4], hq[5], hq[6], hq[7]);
            *(uint4*)(smem + G2_CAL + d)      = make_uint4(lq[0], lq[1], lq[2], lq[3]);
            *(uint4*)(smem + G2_CAL + d + 16) = make_uint4(lq[4], lq[5], lq[6], lq[7]);
        }
        __syncthreads();
        #pragma unroll
        for (int s = 0; s < 2; s++) {
            const int kc = s * 16;
            uint32_t fAh[4][4], fAl[4][4];
            #pragma unroll
            for (int mf = 0; mf < 4; mf++) {
                uint32_t off = (uint32_t)(((wm * 64 + mf * 16 + lrow) * 40 + kc + lk) * 2);
                LDSM4(fAh[mf][0], fAh[mf][1], fAh[mf][2], fAh[mf][3], sb + G2_CAH + off);
                LDSM4(fAl[mf][0], fAl[mf][1], fAl[mf][2], fAl[mf][3], sb + G2_CAL + off);
            }
            uint32_t fBh[4][2], fBl[4][2];
            #pragma unroll
            for (int q = 0; q < 2; q++) {
                uint32_t off = (uint32_t)(((wn * 32 + q * 16 + lrow) * 40 + kc + lk) * 2);
                uint32_t r0, r1, r2, r3;
                LDSM4(r0, r1, r2, r3, bufb + G2_BH + off);
                fBh[q*2][0] = r0; fBh[q*2][1] = r2;
                fBh[q*2+1][0] = r1; fBh[q*2+1][1] = r3;
                LDSM4(r0, r1, r2, r3, bufb + G2_BL + off);
                fBl[q*2][0] = r0; fBl[q*2][1] = r2;
                fBl[q*2+1][0] = r1; fBl[q*2+1][1] = r3;
            }
            #pragma unroll
            for (int mf = 0; mf < 4; mf++)
                #pragma unroll
                for (int nf = 0; nf < 4; nf++) {
                    MMA16816(acc[mf][nf], fAh[mf][0], fAh[mf][1], fAh[mf][2], fAh[mf][3],
                             fBh[nf][0], fBh[nf][1]);
                    MMA16816(acc[mf][nf], fAh[mf][0], fAh[mf][1], fAh[mf][2], fAh[mf][3],
                             fBl[nf][0], fBl[nf][1]);
                    MMA16816(acc[mf][nf], fAl[mf][0], fAl[mf][1], fAl[mf][2], fAl[mf][3],
                             fBh[nf][0], fBh[nf][1]);
                }
        }
        __syncthreads();
    }

    // epilogue: write Out + GN2 partial stats
    const int g = lane >> 2, tig = lane & 3;
    float gs[16];
    #pragma unroll
    for (int i = 0; i < 16; i++) gs[i] = 0.0f;
    #pragma unroll
    for (int mf = 0; mf < 4; mf++)
        #pragma unroll
        for (int nf = 0; nf < 4; nf++) {
            int row = m0 + wm * 64 + mf * 16 + g;
            int col = wn * 32 + nf * 8 + tig * 2;
            float d0 = acc[mf][nf][0], d1 = acc[mf][nf][1];
            float d2 = acc[mf][nf][2], d3 = acc[mf][nf][3];
            *(float2*)(Out + (size_t)row * COUT + col)       = make_float2(d0, d1);
            *(float2*)(Out + (size_t)(row + 8) * COUT + col) = make_float2(d2, d3);
            int grp = col >> 4;
            gs[grp]     += d0 + d1 + d2 + d3;
            gs[8 + grp] += d0*d0 + d1*d1 + d2*d2 + d3*d3;
        }
    __syncthreads();
    float* red = (float*)smem;
    #pragma unroll
    for (int i = 0; i < 16; i++) red[i * 256 + tid] = gs[i];
    __syncthreads();
    for (int off = 128; off > 0; off >>= 1) {
        if (tid < off) {
            #pragma unroll
            for (int i = 0; i < 16; i++) red[i * 256 + tid] += red[i * 256 + tid + off];
        }
        __syncthreads();
    }
    if (tid < 16) {
        int cta = blockIdx.x & 127;
        int grp = tid & 7;
        part[(tid >= 8 ? 4096 : 0) + (bb * 8 + grp) * 128 + cta] = red[tid * 256];
    }
}

// ==================== GN final ====================
template<int CPG>
__global__ void stats_final(
    const float* __restrict__ ps, const float* __restrict__ pss,
    const float* __restrict__ gamma, const float* __restrict__ beta,
    float* __restrict__ ac, float* __restrict__ bc, int Cdim)
{
    const int bg = blockIdx.x;
    const int b = bg >> 3, g = bg & 7;
    __shared__ float s_m, s_i;
    if (threadIdx.x == 0) {
        float s = 0.0f, ss = 0.0f;
        for (int i = 0; i < 128; i++) { s += ps[bg * 128 + i]; ss += pss[bg * 128 + i]; }
        float cnt = (float)NPTS * (float)CPG;
        float mu = s / cnt;
        float var = ss / cnt - mu * mu;
        s_m = mu; s_i = rsqrtf(var + EPS_GN);
    }
    __syncthreads();
    int ch = g * CPG + threadIdx.x;
    float a = gamma[ch] * s_i;
    ac[b * Cdim + ch] = a;
    bc[b * Cdim + ch] = beta[ch] - s_m * a;
}

// ==================== finalize ====================
__global__ void __launch_bounds__(256) finalize_kernel(
    float* __restrict__ out, const float* __restrict__ a, const float* __restrict__ bc)
{
    size_t i = (size_t)blockIdx.x * 256 + threadIdx.x;
    int c = (int)(i & 127);
    int b = (int)(i >> 21);
    float v = out[i];
    out[i] = fmaxf(fmaf(v, a[b * COUT + c], bc[b * COUT + c]), 0.0f);
}

// ==================== launch ====================
extern "C" void kernel_launch(void* const* d_in, const int* in_sizes, int n_in,
                              void* d_out, int out_size)
{
    const float* fine_xyz    = (const float*)d_in[0];
    const float* coarse_xyz  = (const float*)d_in[1];
    const float* fine_feat   = (const float*)d_in[2];
    const float* coarse_feat = (const float*)d_in[3];
    const float* w1          = (const float*)d_in[4];
    const float* g1_w        = (const float*)d_in[5];
    const float* g1_b        = (const float*)d_in[6];
    const float* w2          = (const float*)d_in[7];
    const float* g2_w        = (const float*)d_in[8];
    const float* g2_b        = (const float*)d_in[9];
    float* out = (float*)d_out;

    __half *chi, *clo, *w1h, *w1l, *w2h, *w2l;
    float *h1, *wt, *part1, *part2, *a1, *b1, *a2, *b2;
    int* idx;
    cudaGetSymbolAddress((void**)&chi, g_comb_hi);
    cudaGetSymbolAddress((void**)&clo, g_comb_lo);
    cudaGetSymbolAddress((void**)&h1, g_h1);
    cudaGetSymbolAddress((void**)&idx, g_idx);
    cudaGetSymbolAddress((void**)&wt, g_wt);
    cudaGetSymbolAddress((void**)&w1h, g_w1h);
    cudaGetSymbolAddress((void**)&w1l, g_w1l);
    cudaGetSymbolAddress((void**)&w2h, g_w2h);
    cudaGetSymbolAddress((void**)&w2l, g_w2l);
    cudaGetSymbolAddress((void**)&part1, g_part1);
    cudaGetSymbolAddress((void**)&part2, g_part2);
    cudaGetSymbolAddress((void**)&a1, g_a1);
    cudaGetSymbolAddress((void**)&b1, g_b1);
    cudaGetSymbolAddress((void**)&a2, g_a2);
    cudaGetSymbolAddress((void**)&b2, g_b2);

    cudaFuncSetAttribute(gemm1_mma, cudaFuncAttributeMaxDynamicSharedMemorySize, G1_SMEM);
    cudaFuncSetAttribute(gemm2_mma, cudaFuncAttributeMaxDynamicSharedMemorySize, G2_SMEM);

    knn_kernel<<<dim3(NPTS / 256, BATCH), 128>>>(fine_xyz, coarse_xyz, idx, wt);
    prep_weights<<<(CMID * CIN + COUT * CMID + 255) / 256, 256>>>(w1, w2, w1h, w1l, w2h, w2l);
    interp_kernel<<<BN_TOTAL / 8, 256>>>(fine_feat, coarse_feat, idx, wt, chi, clo);
    gemm1_mma<<<BN_TOTAL / 128, 256, G1_SMEM>>>(chi, clo, w1h, w1l, h1, part1);
    stats_final<CMID / GROUPS><<<BATCH * GROUPS, CMID / GROUPS>>>(part1, part1 + 4096, g1_w, g1_b, a1, b1, CMID);
    gemm2_mma<<<BN_TOTAL / 128, 256, G2_SMEM>>>(h1, w2h, w2l, a1, b1, out, part2);
    stats_final<COUT / GROUPS><<<BATCH * GROUPS, COUT / GROUPS>>>(part2, part2 + 4096, g2_w, g2_b, a2, b2, COUT);
    finalize_kernel<<<(BN_TOTAL * COUT) / 256, 256>>>(out, a2, b2);
}

// round 7
// speedup vs baseline: 1.0892x; 1.0892x over previous
#include <cuda_runtime.h>
#include <cuda_fp16.h>
#include <cstdint>
#include <cstddef>

// Problem constants
#define BATCH 4
#define NPTS  16384
#define SPTS  4096
#define CF    128
#define CC    256
#define CIN   384
#define CMID  192
#define COUT  128
#define GROUPS 8
#define EPS_GN 1e-5f
#define EPS_D  1e-8f
#define BN_TOTAL (BATCH * NPTS)   // 65536
#define CTAS_PER_BATCH 128

// -------------------- scratch (device globals; no allocation) --------------------
__device__ __align__(16) __half g_comb_hi[(size_t)BN_TOTAL * CIN];
__device__ __align__(16) __half g_comb_lo[(size_t)BN_TOTAL * CIN];
__device__ __align__(16) float  g_h1[(size_t)BN_TOTAL * CMID];
__device__ int   g_idx[(size_t)BN_TOTAL * 3];
__device__ float g_wt[(size_t)BN_TOTAL * 3];
__device__ __align__(16) __half g_w1h[CMID * CIN], g_w1l[CMID * CIN];
__device__ __align__(16) __half g_w2h[COUT * CMID], g_w2l[COUT * CMID];
__device__ float g_part1[2 * 32 * CTAS_PER_BATCH];
__device__ float g_part2[2 * 32 * CTAS_PER_BATCH];
__device__ float g_a1[BATCH * CMID], g_b1[BATCH * CMID];
__device__ float g_a2[BATCH * COUT], g_b2[BATCH * COUT];

// ==================== helpers ====================
__device__ __forceinline__ uint32_t smem_u32(const void* p) {
    uint32_t a;
    asm("{ .reg .u64 t; cvta.to.shared.u64 t, %1; cvt.u32.u64 %0, t; }" : "=r"(a) : "l"(p));
    return a;
}
#define LDSM4(r0, r1, r2, r3, addr) \
    asm volatile("ldmatrix.sync.aligned.m8n8.x4.shared.b16 {%0,%1,%2,%3}, [%4];" \
        : "=r"(r0), "=r"(r1), "=r"(r2), "=r"(r3) : "r"(addr))
#define MMA16816(d, a0, a1, a2, a3, b0, b1) \
    asm volatile("mma.sync.aligned.m16n8k16.row.col.f32.f16.f16.f32 " \
        "{%0,%1,%2,%3},{%4,%5,%6,%7},{%8,%9},{%0,%1,%2,%3};" \
        : "+f"((d)[0]), "+f"((d)[1]), "+f"((d)[2]), "+f"((d)[3]) \
        : "r"(a0), "r"(a1), "r"(a2), "r"(a3), "r"(b0), "r"(b1))
#define CP16(dst, src) \
    asm volatile("cp.async.cg.shared.global [%0], [%1], 16;" :: "r"(dst), "l"(src))
#define CP_COMMIT() asm volatile("cp.async.commit_group;" ::: "memory")
#define CP_WAIT1()  asm volatile("cp.async.wait_group 1;" ::: "memory")

__device__ __forceinline__ void split2(float x, float y, uint32_t& h, uint32_t& l) {
    __half hx = __float2half_rn(x), hy = __float2half_rn(y);
    __half lx = __float2half_rn(x - __half2float(hx));
    __half ly = __float2half_rn(y - __half2float(hy));
    h = ((uint32_t)__half_as_ushort(hy) << 16) | __half_as_ushort(hx);
    l = ((uint32_t)__half_as_ushort(ly) << 16) | __half_as_ushort(lx);
}

// ==================== Kernel 1: kNN (K=3) + IDW weights (1 query/thread) ====================
#define KNN_CHUNK 2048
__global__ void __launch_bounds__(128) knn_kernel(
    const float* __restrict__ fxyz, const float* __restrict__ cxyz,
    int* __restrict__ oidx, float* __restrict__ owt)
{
    __shared__ float4 cs[KNN_CHUNK];
    const int b = blockIdx.y;
    const int n = blockIdx.x * 128 + threadIdx.x;
    const float* fp = fxyz + ((size_t)b * NPTS + n) * 3;
    const float qx = fp[0], qy = fp[1], qz = fp[2];
    const float qn = qx*qx + qy*qy + qz*qz;

    float s0 = 3.4e38f, s1 = 3.4e38f, s2 = 3.4e38f;
    int   i0 = 0, i1 = 0, i2 = 0;

    for (int c0 = 0; c0 < SPTS; c0 += KNN_CHUNK) {
        __syncthreads();
        for (int j = threadIdx.x; j < KNN_CHUNK; j += 128) {
            const float* cp = cxyz + ((size_t)b * SPTS + c0 + j) * 3;
            float x = cp[0], y = cp[1], z = cp[2];
            cs[j] = make_float4(x, y, z, x*x + y*y + z*z);
        }
        __syncthreads();
        #pragma unroll 8
        for (int j = 0; j < KNN_CHUNK; j++) {
            float4 c = cs[j];
            float dot = qx*c.x + qy*c.y + qz*c.z;
            float score = fmaf(-2.0f, dot, qn + c.w);   // reference ranking formula
            if (score < s2) {
                int idx = c0 + j;
                if (score < s1) {
                    s2 = s1; i2 = i1;
                    if (score < s0) { s1 = s0; i1 = i0; s0 = score; i0 = idx; }
                    else            { s1 = score; i1 = idx; }
                } else { s2 = score; i2 = idx; }
            }
        }
    }
    int ii[3] = { i0, i1, i2 };
    float w[3], wsum = 0.0f;
    #pragma unroll
    for (int k = 0; k < 3; k++) {
        const float* cp = cxyz + ((size_t)b * SPTS + ii[k]) * 3;
        float dx = qx - cp[0], dy = qy - cp[1], dz = qz - cp[2];
        float d2 = fmaxf(dx*dx + dy*dy + dz*dz, EPS_D);
        w[k] = 1.0f / d2; wsum += w[k];
    }
    float inv = 1.0f / wsum;
    size_t base = ((size_t)b * NPTS + n) * 3;
    #pragma unroll
    for (int k = 0; k < 3; k++) { oidx[base + k] = ii[k]; owt[base + k] = w[k] * inv; }
}

// ==================== Kernel 2: weights fp32 -> fp16 hi/lo ====================
__global__ void prep_weights(const float* __restrict__ w1, const float* __restrict__ w2,
                             __half* w1h, __half* w1l, __half* w2h, __half* w2l)
{
    int i = blockIdx.x * 256 + threadIdx.x;
    if (i < CMID * CIN) {
        float x = w1[i];
        __half h = __float2half_rn(x);
        w1h[i] = h; w1l[i] = __float2half_rn(x - __half2float(h));
    }
    int j = i - CMID * CIN;
    if (j >= 0 && j < COUT * CMID) {
        float x = w2[j];
        __half h = __float2half_rn(x);
        w2h[j] = h; w2l[j] = __float2half_rn(x - __half2float(h));
    }
}

// ==================== Kernel 3: interp + concat -> fp16 hi/lo ====================
__global__ void __launch_bounds__(256) interp_kernel(
    const float* __restrict__ ffeat, const float* __restrict__ cfeat,
    const int* __restrict__ idx, const float* __restrict__ wt,
    __half* __restrict__ chi, __half* __restrict__ clo)
{
    const int gwarp = (blockIdx.x * 256 + threadIdx.x) >> 5;
    const int lane  = threadIdx.x & 31;
    const size_t p  = (size_t)gwarp;
    const int b     = (int)(p >> 14);

    const int*   ip = idx + p * 3;
    const float* wp = wt  + p * 3;
    int   j0 = ip[0], j1 = ip[1], j2 = ip[2];
    float w0 = wp[0], w1v = wp[1], w2v = wp[2];

    char* hbase = (char*)(chi + p * CIN);
    char* lbase = (char*)(clo + p * CIN);
    const float4* f4 = (const float4*)(ffeat + p * CF);
    {
        float4 v = f4[lane];
        uint32_t h0, l0, h1, l1;
        split2(v.x, v.y, h0, l0); split2(v.z, v.w, h1, l1);
        *(uint2*)(hbase + lane * 8) = make_uint2(h0, h1);
        *(uint2*)(lbase + lane * 8) = make_uint2(l0, l1);
    }
    const float4* c0 = (const float4*)(cfeat + ((size_t)b * SPTS + j0) * CC);
    const float4* c1 = (const float4*)(cfeat + ((size_t)b * SPTS + j1) * CC);
    const float4* c2 = (const float4*)(cfeat + ((size_t)b * SPTS + j2) * CC);
    #pragma unroll
    for (int t = 0; t < 2; t++) {
        int c = t * 32 + lane;
        float4 A = c0[c], B = c1[c], Cv = c2[c];
        float4 r;
        r.x = w0*A.x + w1v*B.x + w2v*Cv.x;
        r.y = w0*A.y + w1v*B.y + w2v*Cv.y;
        r.z = w0*A.z + w1v*B.z + w2v*Cv.z;
        r.w = w0*A.w + w1v*B.w + w2v*Cv.w;
        uint32_t h0, l0, h1, l1;
        split2(r.x, r.y, h0, l0); split2(r.z, r.w, h1, l1);
        *(uint2*)(hbase + 256 + c * 8) = make_uint2(h0, h1);
        *(uint2*)(lbase + 256 + c * 8) = make_uint2(l0, l1);
    }
}

// ==================== GEMM1: 512 threads (4 warps/SMSP), 3-stage cp.async, fp16x3 ====================
// CTA tile 128x192, warp grid 4x4 (warp tile 32x48), BK=32, stage = 51200 B
#define G1_STAGE 51200
#define G1_AH 0
#define G1_AL 10240
#define G1_BH 20480
#define G1_BL 35840
#define G1_SMEM (3 * G1_STAGE)   // 153600

__global__ void __launch_bounds__(512) gemm1_mma(
    const __half* __restrict__ Ah, const __half* __restrict__ Al,
    const __half* __restrict__ Bh, const __half* __restrict__ Bl,
    float* __restrict__ C, float* __restrict__ part)
{
    extern __shared__ char smem[];
    const uint32_t sb = smem_u32(smem);
    const int tid = threadIdx.x, lane = tid & 31, wid = tid >> 5;
    const int wm = wid & 3, wn = wid >> 2;          // warp grid 4 x 4
    const int m0 = blockIdx.x * 128;

    auto issue = [&](int it, int buf) {
        const int kc0 = it * 32;
        const uint32_t base = sb + buf * G1_STAGE;
        {   // A hi/lo: 512 CP16 each, 1 per thread
            int row = tid >> 2, ko = (tid & 3) * 8;
            uint32_t d = base + row * 80 + ko * 2;
            CP16(d + G1_AH, Ah + (size_t)(m0 + row) * CIN + kc0 + ko);
            CP16(d + G1_AL, Al + (size_t)(m0 + row) * CIN + kc0 + ko);
        }
        #pragma unroll
        for (int q = 0; q < 3; q++) {    // B hi (768 ops) then lo (768 ops)
            int i = q * 512 + tid;
            bool lo = (i >= 768);
            int j = lo ? i - 768 : i;
            int row = j >> 2, ko = (j & 3) * 8;
            uint32_t d = base + (lo ? G1_BL : G1_BH) + row * 80 + ko * 2;
            const __half* src = (lo ? Bl : Bh) + (size_t)row * CIN + kc0 + ko;
            CP16(d, src);
        }
    };

    float acc[2][6][4];
    #pragma unroll
    for (int i = 0; i < 2; i++)
        #pragma unroll
        for (int j = 0; j < 6; j++)
            #pragma unroll
            for (int k = 0; k < 4; k++) acc[i][j][k] = 0.0f;

    issue(0, 0); CP_COMMIT();
    issue(1, 1); CP_COMMIT();

    const int lrow = lane & 15, lk = (lane >> 4) * 8;
    for (int it = 0; it < 12; it++) {
        CP_WAIT1();
        __syncthreads();
        if (it + 2 < 12) issue(it + 2, (it + 2) % 3);
        CP_COMMIT();                 // empty group at drain keeps the count aligned
        const uint32_t bufb = sb + (it % 3) * G1_STAGE;
        #pragma unroll
        for (int s = 0; s < 2; s++) {
            const int kc = s * 16;
            uint32_t fAh[2][4], fAl[2][4];
            #pragma unroll
            for (int mf = 0; mf < 2; mf++) {
                uint32_t off = (uint32_t)(((wm * 32 + mf * 16 + lrow) * 40 + kc + lk) * 2);
                LDSM4(fAh[mf][0], fAh[mf][1], fAh[mf][2], fAh[mf][3], bufb + G1_AH + off);
                LDSM4(fAl[mf][0], fAl[mf][1], fAl[mf][2], fAl[mf][3], bufb + G1_AL + off);
            }
            uint32_t fBh[6][2], fBl[6][2];
            #pragma unroll
            for (int q = 0; q < 3; q++) {
                uint32_t off = (uint32_t)(((wn * 48 + q * 16 + lrow) * 40 + kc + lk) * 2);
                uint32_t r0, r1, r2, r3;
                LDSM4(r0, r1, r2, r3, bufb + G1_BH + off);
                fBh[q*2][0] = r0; fBh[q*2][1] = r2;
                fBh[q*2+1][0] = r1; fBh[q*2+1][1] = r3;
                LDSM4(r0, r1, r2, r3, bufb + G1_BL + off);
                fBl[q*2][0] = r0; fBl[q*2][1] = r2;
                fBl[q*2+1][0] = r1; fBl[q*2+1][1] = r3;
            }
            #pragma unroll
            for (int mf = 0; mf < 2; mf++)
                #pragma unroll
                for (int nf = 0; nf < 6; nf++) {
                    MMA16816(acc[mf][nf], fAh[mf][0], fAh[mf][1], fAh[mf][2], fAh[mf][3],
                             fBh[nf][0], fBh[nf][1]);
                    MMA16816(acc[mf][nf], fAh[mf][0], fAh[mf][1], fAh[mf][2], fAh[mf][3],
                             fBl[nf][0], fBl[nf][1]);
                    MMA16816(acc[mf][nf], fAl[mf][0], fAl[mf][1], fAl[mf][2], fAl[mf][3],
                             fBh[nf][0], fBh[nf][1]);
                }
        }
        __syncthreads();
    }

    // epilogue: write C + GN1 partial stats from accumulators
    const int g = lane >> 2, tig = lane & 3;
    float gs[16];
    #pragma unroll
    for (int i = 0; i < 16; i++) gs[i] = 0.0f;
    #pragma unroll
    for (int mf = 0; mf < 2; mf++)
        #pragma unroll
        for (int nf = 0; nf < 6; nf++) {
            int row = m0 + wm * 32 + mf * 16 + g;
            int col = wn * 48 + nf * 8 + tig * 2;
            float d0 = acc[mf][nf][0], d1 = acc[mf][nf][1];
            float d2 = acc[mf][nf][2], d3 = acc[mf][nf][3];
            *(float2*)(C + (size_t)row * CMID + col)       = make_float2(d0, d1);
            *(float2*)(C + (size_t)(row + 8) * CMID + col) = make_float2(d2, d3);
            int grp = col / 24;
            gs[grp]     += d0 + d1 + d2 + d3;
            gs[8 + grp] += d0*d0 + d1*d1 + d2*d2 + d3*d3;
        }
    __syncthreads();
    float* red = (float*)smem;
    #pragma unroll
    for (int i = 0; i < 16; i++) red[i * 512 + tid] = gs[i];
    __syncthreads();
    for (int off = 256; off > 0; off >>= 1) {
        if (tid < off) {
            #pragma unroll
            for (int i = 0; i < 16; i++) red[i * 512 + tid] += red[i * 512 + tid + off];
        }
        __syncthreads();
    }
    if (tid < 16) {
        int b = blockIdx.x >> 7, cta = blockIdx.x & 127;
        int grp = tid & 7;
        part[(tid >= 8 ? 4096 : 0) + (b * 8 + grp) * 128 + cta] = red[tid * 512];
    }
}

// ==================== GEMM2 (R4 version): reg-prefetch, GN1 affine+relu fused, GN2 stats ====================
// CTA 128x128, warps 2x4 (64x32), BK=32
#define G2_AH 0
#define G2_AL 10240
#define G2_BH 20480
#define G2_BL 30720
#define G2_AFF 40960
#define G2_SMEM (G2_AFF + 2 * CMID * 4)

__global__ void __launch_bounds__(256) gemm2_mma(
    const float* __restrict__ H,
    const __half* __restrict__ Bh, const __half* __restrict__ Bl,
    const float* __restrict__ a1, const float* __restrict__ b1,
    float* __restrict__ Out, float* __restrict__ part)
{
    extern __shared__ char smem[];
    const uint32_t sb = smem_u32(smem);
    const int tid = threadIdx.x, lane = tid & 31, wid = tid >> 5;
    const int wm = wid & 1, wn = wid >> 1;
    const int m0 = blockIdx.x * 128;
    const int bb = blockIdx.x >> 7;

    float* s_a = (float*)(smem + G2_AFF);
    float* s_b = s_a + CMID;
    for (int i = tid; i < CMID; i += 256) { s_a[i] = a1[bb * CMID + i]; s_b[i] = b1[bb * CMID + i]; }
    __syncthreads();

    const int arow = tid >> 1, akoff = (tid & 1) * 16;

    float acc[4][4][4];
    #pragma unroll
    for (int i = 0; i < 4; i++)
        #pragma unroll
        for (int j = 0; j < 4; j++)
            #pragma unroll
            for (int k = 0; k < 4; k++) acc[i][j][k] = 0.0f;

    uint4 aH[2], aL[2], bH[2], bL[2];
    auto loadG = [&](int it) {
        int kc0 = it * 32;
        const float* hrow = H + (size_t)(m0 + arow) * CMID + kc0 + akoff;
        uint32_t hq[8], lq[8];
        #pragma unroll
        for (int e = 0; e < 8; e++) {
            int c = kc0 + akoff + e * 2;
            float x = fmaxf(fmaf(hrow[e*2],   s_a[c],   s_b[c]),   0.0f);
            float y = fmaxf(fmaf(hrow[e*2+1], s_a[c+1], s_b[c+1]), 0.0f);
            split2(x, y, hq[e], lq[e]);
        }
        aH[0] = make_uint4(hq[0], hq[1], hq[2], hq[3]);
        aH[1] = make_uint4(hq[4], hq[5], hq[6], hq[7]);
        aL[0] = make_uint4(lq[0], lq[1], lq[2], lq[3]);
        aL[1] = make_uint4(lq[4], lq[5], lq[6], lq[7]);
        bH[0] = *(const uint4*)(Bh + (size_t)arow * CMID + kc0 + akoff);
        bH[1] = *(const uint4*)(Bh + (size_t)arow * CMID + kc0 + akoff + 8);
        bL[0] = *(const uint4*)(Bl + (size_t)arow * CMID + kc0 + akoff);
        bL[1] = *(const uint4*)(Bl + (size_t)arow * CMID + kc0 + akoff + 8);
    };
    auto storeS = [&]() {
        *(uint4*)(smem + G2_AH + arow * 80 + akoff * 2)      = aH[0];
        *(uint4*)(smem + G2_AH + arow * 80 + akoff * 2 + 16) = aH[1];
        *(uint4*)(smem + G2_AL + arow * 80 + akoff * 2)      = aL[0];
        *(uint4*)(smem + G2_AL + arow * 80 + akoff * 2 + 16) = aL[1];
        *(uint4*)(smem + G2_BH + arow * 80 + akoff * 2)      = bH[0];
        *(uint4*)(smem + G2_BH + arow * 80 + akoff * 2 + 16) = bH[1];
        *(uint4*)(smem + G2_BL + arow * 80 + akoff * 2)      = bL[0];
        *(uint4*)(smem + G2_BL + arow * 80 + akoff * 2 + 16) = bL[1];
    };

    const int lrow = lane & 15, lk = (lane >> 4) * 8;
    loadG(0);
    for (int it = 0; it < 6; it++) {
        storeS();
        __syncthreads();
        if (it < 5) loadG(it + 1);
        #pragma unroll
        for (int s = 0; s < 2; s++) {
            const int kc = s * 16;
            uint32_t fAh[4][4], fAl[4][4];
            #pragma unroll
            for (int mf = 0; mf < 4; mf++) {
                uint32_t off = (uint32_t)(((wm * 64 + mf * 16 + lrow) * 40 + kc + lk) * 2);
                LDSM4(fAh[mf][0], fAh[mf][1], fAh[mf][2], fAh[mf][3], sb + G2_AH + off);
                LDSM4(fAl[mf][0], fAl[mf][1], fAl[mf][2], fAl[mf][3], sb + G2_AL + off);
            }
            uint32_t fBh[4][2], fBl[4][2];
            #pragma unroll
            for (int q = 0; q < 2; q++) {
                uint32_t off = (uint32_t)(((wn * 32 + q * 16 + lrow) * 40 + kc + lk) * 2);
                uint32_t r0, r1, r2, r3;
                LDSM4(r0, r1, r2, r3, sb + G2_BH + off);
                fBh[q*2][0] = r0; fBh[q*2][1] = r2;
                fBh[q*2+1][0] = r1; fBh[q*2+1][1] = r3;
                LDSM4(r0, r1, r2, r3, sb + G2_BL + off);
                fBl[q*2][0] = r0; fBl[q*2][1] = r2;
                fBl[q*2+1][0] = r1; fBl[q*2+1][1] = r3;
            }
            #pragma unroll
            for (int mf = 0; mf < 4; mf++)
                #pragma unroll
                for (int nf = 0; nf < 4; nf++) {
                    MMA16816(acc[mf][nf], fAh[mf][0], fAh[mf][1], fAh[mf][2], fAh[mf][3],
                             fBh[nf][0], fBh[nf][1]);
                    MMA16816(acc[mf][nf], fAh[mf][0], fAh[mf][1], fAh[mf][2], fAh[mf][3],
                             fBl[nf][0], fBl[nf][1]);
                    MMA16816(acc[mf][nf], fAl[mf][0], fAl[mf][1], fAl[mf][2], fAl[mf][3],
                             fBh[nf][0], fBh[nf][1]);
                }
        }
        __syncthreads();
    }

    // epilogue: write Out + GN2 partial stats
    const int g = lane >> 2, tig = lane & 3;
    float gs[16];
    #pragma unroll
    for (int i = 0; i < 16; i++) gs[i] = 0.0f;
    #pragma unroll
    for (int mf = 0; mf < 4; mf++)
        #pragma unroll
        for (int nf = 0; nf < 4; nf++) {
            int row = m0 + wm * 64 + mf * 16 + g;
            int col = wn * 32 + nf * 8 + tig * 2;
            float d0 = acc[mf][nf][0], d1 = acc[mf][nf][1];
            float d2 = acc[mf][nf][2], d3 = acc[mf][nf][3];
            *(float2*)(Out + (size_t)row * COUT + col)       = make_float2(d0, d1);
            *(float2*)(Out + (size_t)(row + 8) * COUT + col) = make_float2(d2, d3);
            int grp = col >> 4;
            gs[grp]     += d0 + d1 + d2 + d3;
            gs[8 + grp] += d0*d0 + d1*d1 + d2*d2 + d3*d3;
        }
    __syncthreads();
    float* red = (float*)smem;
    #pragma unroll
    for (int i = 0; i < 16; i++) red[i * 256 + tid] = gs[i];
    __syncthreads();
    for (int off = 128; off > 0; off >>= 1) {
        if (tid < off) {
            #pragma unroll
            for (int i = 0; i < 16; i++) red[i * 256 + tid] += red[i * 256 + tid + off];
        }
        __syncthreads();
    }
    if (tid < 16) {
        int cta = blockIdx.x & 127;
        int grp = tid & 7;
        part[(tid >= 8 ? 4096 : 0) + (bb * 8 + grp) * 128 + cta] = red[tid * 256];
    }
}

// ==================== GN final ====================
template<int CPG>
__global__ void stats_final(
    const float* __restrict__ ps, const float* __restrict__ pss,
    const float* __restrict__ gamma, const float* __restrict__ beta,
    float* __restrict__ ac, float* __restrict__ bc, int Cdim)
{
    const int bg = blockIdx.x;
    const int b = bg >> 3, g = bg & 7;
    __shared__ float s_m, s_i;
    if (threadIdx.x == 0) {
        float s = 0.0f, ss = 0.0f;
        for (int i = 0; i < 128; i++) { s += ps[bg * 128 + i]; ss += pss[bg * 128 + i]; }
        float cnt = (float)NPTS * (float)CPG;
        float mu = s / cnt;
        float var = ss / cnt - mu * mu;
        s_m = mu; s_i = rsqrtf(var + EPS_GN);
    }
    __syncthreads();
    int ch = g * CPG + threadIdx.x;
    float a = gamma[ch] * s_i;
    ac[b * Cdim + ch] = a;
    bc[b * Cdim + ch] = beta[ch] - s_m * a;
}

// ==================== finalize ====================
__global__ void __launch_bounds__(256) finalize_kernel(
    float* __restrict__ out, const float* __restrict__ a, const float* __restrict__ bc)
{
    size_t i = (size_t)blockIdx.x * 256 + threadIdx.x;
    int c = (int)(i & 127);
    int b = (int)(i >> 21);
    float v = out[i];
    out[i] = fmaxf(fmaf(v, a[b * COUT + c], bc[b * COUT + c]), 0.0f);
}

// ==================== launch ====================
extern "C" void kernel_launch(void* const* d_in, const int* in_sizes, int n_in,
                              void* d_out, int out_size)
{
    const float* fine_xyz    = (const float*)d_in[0];
    const float* coarse_xyz  = (const float*)d_in[1];
    const float* fine_feat   = (const float*)d_in[2];
    const float* coarse_feat = (const float*)d_in[3];
    const float* w1          = (const float*)d_in[4];
    const float* g1_w        = (const float*)d_in[5];
    const float* g1_b        = (const float*)d_in[6];
    const float* w2          = (const float*)d_in[7];
    const float* g2_w        = (const float*)d_in[8];
    const float* g2_b        = (const float*)d_in[9];
    float* out = (float*)d_out;

    __half *chi, *clo, *w1h, *w1l, *w2h, *w2l;
    float *h1, *wt, *part1, *part2, *a1, *b1, *a2, *b2;
    int* idx;
    cudaGetSymbolAddress((void**)&chi, g_comb_hi);
    cudaGetSymbolAddress((void**)&clo, g_comb_lo);
    cudaGetSymbolAddress((void**)&h1, g_h1);
    cudaGetSymbolAddress((void**)&idx, g_idx);
    cudaGetSymbolAddress((void**)&wt, g_wt);
    cudaGetSymbolAddress((void**)&w1h, g_w1h);
    cudaGetSymbolAddress((void**)&w1l, g_w1l);
    cudaGetSymbolAddress((void**)&w2h, g_w2h);
    cudaGetSymbolAddress((void**)&w2l, g_w2l);
    cudaGetSymbolAddress((void**)&part1, g_part1);
    cudaGetSymbolAddress((void**)&part2, g_part2);
    cudaGetSymbolAddress((void**)&a1, g_a1);
    cudaGetSymbolAddress((void**)&b1, g_b1);
    cudaGetSymbolAddress((void**)&a2, g_a2);
    cudaGetSymbolAddress((void**)&b2, g_b2);

    cudaFuncSetAttribute(gemm1_mma, cudaFuncAttributeMaxDynamicSharedMemorySize, G1_SMEM);
    cudaFuncSetAttribute(gemm2_mma, cudaFuncAttributeMaxDynamicSharedMemorySize, G2_SMEM);

    knn_kernel<<<dim3(NPTS / 128, BATCH), 128>>>(fine_xyz, coarse_xyz, idx, wt);
    prep_weights<<<(CMID * CIN + COUT * CMID + 255) / 256, 256>>>(w1, w2, w1h, w1l, w2h, w2l);
    interp_kernel<<<BN_TOTAL / 8, 256>>>(fine_feat, coarse_feat, idx, wt, chi, clo);
    gemm1_mma<<<BN_TOTAL / 128, 512, G1_SMEM>>>(chi, clo, w1h, w1l, h1, part1);
    stats_final<CMID / GROUPS><<<BATCH * GROUPS, CMID / GROUPS>>>(part1, part1 + 4096, g1_w, g1_b, a1, b1, CMID);
    gemm2_mma<<<BN_TOTAL / 128, 256, G2_SMEM>>>(h1, w2h, w2l, a1, b1, out, part2);
    stats_final<COUT / GROUPS><<<BATCH * GROUPS, COUT / GROUPS>>>(part2, part2 + 4096, g2_w, g2_b, a2, b2, COUT);
    finalize_kernel<<<(BN_TOTAL * COUT) / 256, 256>>>(out, a2, b2);
}

// round 9
// speedup vs baseline: 1.3256x; 1.2171x over previous
#include <cuda_runtime.h>
#include <cuda_fp16.h>
#include <cstdint>
#include <cstddef>

// Problem constants
#define BATCH 4
#define NPTS  16384
#define SPTS  4096
#define CF    128
#define CC    256
#define CIN   384
#define CMID  192
#define COUT  128
#define GROUPS 8
#define EPS_GN 1e-5f
#define EPS_D  1e-8f
#define BN_TOTAL (BATCH * NPTS)   // 65536
#define CTAS_PER_BATCH 128

// -------------------- scratch (device globals; no allocation) --------------------
__device__ __align__(16) __half g_comb_hi[(size_t)BN_TOTAL * CIN];
__device__ __align__(16) float  g_h1[(size_t)BN_TOTAL * CMID];
__device__ int   g_idx[(size_t)BN_TOTAL * 3];
__device__ float g_wt[(size_t)BN_TOTAL * 3];
__device__ __align__(16) __half g_w1h[CMID * CIN];
__device__ __align__(16) __half g_w2h[COUT * CMID], g_w2l[COUT * CMID];
__device__ float g_part1[2 * 32 * CTAS_PER_BATCH];
__device__ float g_part2[2 * 32 * CTAS_PER_BATCH];
__device__ float g_a1[BATCH * CMID], g_b1[BATCH * CMID];
__device__ float g_a2[BATCH * COUT], g_b2[BATCH * COUT];

// ==================== helpers ====================
__device__ __forceinline__ uint32_t smem_u32(const void* p) {
    uint32_t a;
    asm("{ .reg .u64 t; cvta.to.shared.u64 t, %1; cvt.u32.u64 %0, t; }" : "=r"(a) : "l"(p));
    return a;
}
#define LDSM4(r0, r1, r2, r3, addr) \
    asm volatile("ldmatrix.sync.aligned.m8n8.x4.shared.b16 {%0,%1,%2,%3}, [%4];" \
        : "=r"(r0), "=r"(r1), "=r"(r2), "=r"(r3) : "r"(addr))
#define MMA16816(d, a0, a1, a2, a3, b0, b1) \
    asm volatile("mma.sync.aligned.m16n8k16.row.col.f32.f16.f16.f32 " \
        "{%0,%1,%2,%3},{%4,%5,%6,%7},{%8,%9},{%0,%1,%2,%3};" \
        : "+f"((d)[0]), "+f"((d)[1]), "+f"((d)[2]), "+f"((d)[3]) \
        : "r"(a0), "r"(a1), "r"(a2), "r"(a3), "r"(b0), "r"(b1))
#define CP16(dst, src) \
    asm volatile("cp.async.cg.shared.global [%0], [%1], 16;" :: "r"(dst), "l"(src))
#define CP_COMMIT() asm volatile("cp.async.commit_group;" ::: "memory")
#define CP_WAIT1()  asm volatile("cp.async.wait_group 1;" ::: "memory")

__device__ __forceinline__ void split2(float x, float y, uint32_t& h, uint32_t& l) {
    __half hx = __float2half_rn(x), hy = __float2half_rn(y);
    __half lx = __float2half_rn(x - __half2float(hx));
    __half ly = __float2half_rn(y - __half2float(hy));
    h = ((uint32_t)__half_as_ushort(hy) << 16) | __half_as_ushort(hx);
    l = ((uint32_t)__half_as_ushort(ly) << 16) | __half_as_ushort(lx);
}
__device__ __forceinline__ uint32_t pack2(float x, float y) {
    __half hx = __float2half_rn(x), hy = __float2half_rn(y);
    return ((uint32_t)__half_as_ushort(hy) << 16) | __half_as_ushort(hx);
}

// ==================== Kernel 1: kNN (K=3) + IDW weights (1 query/thread) ====================
#define KNN_CHUNK 2048
__global__ void __launch_bounds__(128) knn_kernel(
    const float* __restrict__ fxyz, const float* __restrict__ cxyz,
    int* __restrict__ oidx, float* __restrict__ owt)
{
    __shared__ float4 cs[KNN_CHUNK];
    const int b = blockIdx.y;
    const int n = blockIdx.x * 128 + threadIdx.x;
    const float* fp = fxyz + ((size_t)b * NPTS + n) * 3;
    const float qx = fp[0], qy = fp[1], qz = fp[2];
    const float qn = qx*qx + qy*qy + qz*qz;

    float s0 = 3.4e38f, s1 = 3.4e38f, s2 = 3.4e38f;
    int   i0 = 0, i1 = 0, i2 = 0;

    for (int c0 = 0; c0 < SPTS; c0 += KNN_CHUNK) {
        __syncthreads();
        for (int j = threadIdx.x; j < KNN_CHUNK; j += 128) {
            const float* cp = cxyz + ((size_t)b * SPTS + c0 + j) * 3;
            float x = cp[0], y = cp[1], z = cp[2];
            cs[j] = make_float4(x, y, z, x*x + y*y + z*z);
        }
        __syncthreads();
        #pragma unroll 8
        for (int j = 0; j < KNN_CHUNK; j++) {
            float4 c = cs[j];
            float dot = qx*c.x + qy*c.y + qz*c.z;
            float score = fmaf(-2.0f, dot, qn + c.w);   // reference ranking formula
            if (score < s2) {
                int idx = c0 + j;
                if (score < s1) {
                    s2 = s1; i2 = i1;
                    if (score < s0) { s1 = s0; i1 = i0; s0 = score; i0 = idx; }
                    else            { s1 = score; i1 = idx; }
                } else { s2 = score; i2 = idx; }
            }
        }
    }
    int ii[3] = { i0, i1, i2 };
    float w[3], wsum = 0.0f;
    #pragma unroll
    for (int k = 0; k < 3; k++) {
        const float* cp = cxyz + ((size_t)b * SPTS + ii[k]) * 3;
        float dx = qx - cp[0], dy = qy - cp[1], dz = qz - cp[2];
        float d2 = fmaxf(dx*dx + dy*dy + dz*dz, EPS_D);
        w[k] = 1.0f / d2; wsum += w[k];
    }
    float inv = 1.0f / wsum;
    size_t base = ((size_t)b * NPTS + n) * 3;
    #pragma unroll
    for (int k = 0; k < 3; k++) { oidx[base + k] = ii[k]; owt[base + k] = w[k] * inv; }
}

// ==================== Kernel 2: weights -> fp16 (w1: hi only; w2: hi/lo) ====================
__global__ void prep_weights(const float* __restrict__ w1, const float* __restrict__ w2,
                             __half* w1h, __half* w2h, __half* w2l)
{
    int i = blockIdx.x * 256 + threadIdx.x;
    if (i < CMID * CIN) {
        w1h[i] = __float2half_rn(w1[i]);
    }
    int j = i - CMID * CIN;
    if (j >= 0 && j < COUT * CMID) {
        float x = w2[j];
        __half h = __float2half_rn(x);
        w2h[j] = h; w2l[j] = __float2half_rn(x - __half2float(h));
    }
}

// ==================== Kernel 3: interp + concat -> fp16 (hi only) ====================
__global__ void __launch_bounds__(256) interp_kernel(
    const float* __restrict__ ffeat, const float* __restrict__ cfeat,
    const int* __restrict__ idx, const float* __restrict__ wt,
    __half* __restrict__ chi)
{
    const int gwarp = (blockIdx.x * 256 + threadIdx.x) >> 5;
    const int lane  = threadIdx.x & 31;
    const size_t p  = (size_t)gwarp;
    const int b     = (int)(p >> 14);

    const int*   ip = idx + p * 3;
    const float* wp = wt  + p * 3;
    int   j0 = ip[0], j1 = ip[1], j2 = ip[2];
    float w0 = wp[0], w1v = wp[1], w2v = wp[2];

    char* hbase = (char*)(chi + p * CIN);
    const float4* f4 = (const float4*)(ffeat + p * CF);
    {
        float4 v = f4[lane];
        *(uint2*)(hbase + lane * 8) = make_uint2(pack2(v.x, v.y), pack2(v.z, v.w));
    }
    const float4* c0 = (const float4*)(cfeat + ((size_t)b * SPTS + j0) * CC);
    const float4* c1 = (const float4*)(cfeat + ((size_t)b * SPTS + j1) * CC);
    const float4* c2 = (const float4*)(cfeat + ((size_t)b * SPTS + j2) * CC);
    #pragma unroll
    for (int t = 0; t < 2; t++) {
        int c = t * 32 + lane;
        float4 A = c0[c], B = c1[c], Cv = c2[c];
        float4 r;
        r.x = w0*A.x + w1v*B.x + w2v*Cv.x;
        r.y = w0*A.y + w1v*B.y + w2v*Cv.y;
        r.z = w0*A.z + w1v*B.z + w2v*Cv.z;
        r.w = w0*A.w + w1v*B.w + w2v*Cv.w;
        *(uint2*)(hbase + 256 + c * 8) = make_uint2(pack2(r.x, r.y), pack2(r.z, r.w));
    }
}

// ==================== GEMM1: single-term fp16, 512 thr, 3-stage cp.async + GN1 stats ====================
// CTA tile 128x192, warp grid 4x4 (warp tile 32x48), BK=32
#define G1_AH 0
#define G1_BH 10240
#define G1_STAGE 25600
#define G1_SMEM (3 * G1_STAGE)   // 76800

__global__ void __launch_bounds__(512) gemm1_mma(
    const __half* __restrict__ Ah, const __half* __restrict__ Bh,
    float* __restrict__ C, float* __restrict__ part)
{
    extern __shared__ char smem[];
    const uint32_t sb = smem_u32(smem);
    const int tid = threadIdx.x, lane = tid & 31, wid = tid >> 5;
    const int wm = wid & 3, wn = wid >> 2;          // warp grid 4 x 4
    const int m0 = blockIdx.x * 128;

    auto issue = [&](int it, int buf) {
        const int kc0 = it * 32;
        const uint32_t base = sb + buf * G1_STAGE;
        {   // A: 512 CP16, 1 per thread
            int row = tid >> 2, ko = (tid & 3) * 8;
            CP16(base + G1_AH + row * 80 + ko * 2, Ah + (size_t)(m0 + row) * CIN + kc0 + ko);
        }
        #pragma unroll
        for (int q = 0; q < 2; q++) {    // B: 768 CP16
            int i = q * 512 + tid;
            if (i < 768) {
                int row = i >> 2, ko = (i & 3) * 8;
                CP16(base + G1_BH + row * 80 + ko * 2, Bh + (size_t)row * CIN + kc0 + ko);
            }
        }
    };

    float acc[2][6][4];
    #pragma unroll
    for (int i = 0; i < 2; i++)
        #pragma unroll
        for (int j = 0; j < 6; j++)
            #pragma unroll
            for (int k = 0; k < 4; k++) acc[i][j][k] = 0.0f;

    issue(0, 0); CP_COMMIT();
    issue(1, 1); CP_COMMIT();

    const int lrow = lane & 15, lk = (lane >> 4) * 8;
    for (int it = 0; it < 12; it++) {
        CP_WAIT1();
        __syncthreads();
        if (it + 2 < 12) issue(it + 2, (it + 2) % 3);
        CP_COMMIT();                 // empty group at drain keeps the count aligned
        const uint32_t bufb = sb + (it % 3) * G1_STAGE;
        #pragma unroll
        for (int s = 0; s < 2; s++) {
            const int kc = s * 16;
            uint32_t fA[2][4];
            #pragma unroll
            for (int mf = 0; mf < 2; mf++) {
                uint32_t off = (uint32_t)(((wm * 32 + mf * 16 + lrow) * 40 + kc + lk) * 2);
                LDSM4(fA[mf][0], fA[mf][1], fA[mf][2], fA[mf][3], bufb + G1_AH + off);
            }
            uint32_t fB[6][2];
            #pragma unroll
            for (int q = 0; q < 3; q++) {
                uint32_t off = (uint32_t)(((wn * 48 + q * 16 + lrow) * 40 + kc + lk) * 2);
                uint32_t r0, r1, r2, r3;
                LDSM4(r0, r1, r2, r3, bufb + G1_BH + off);
                fB[q*2][0] = r0; fB[q*2][1] = r2;
                fB[q*2+1][0] = r1; fB[q*2+1][1] = r3;
            }
            #pragma unroll
            for (int mf = 0; mf < 2; mf++)
                #pragma unroll
                for (int nf = 0; nf < 6; nf++)
                    MMA16816(acc[mf][nf], fA[mf][0], fA[mf][1], fA[mf][2], fA[mf][3],
                             fB[nf][0], fB[nf][1]);
        }
        __syncthreads();
    }

    // epilogue: write C + GN1 partial stats from accumulators
    const int g = lane >> 2, tig = lane & 3;
    float gs[16];
    #pragma unroll
    for (int i = 0; i < 16; i++) gs[i] = 0.0f;
    #pragma unroll
    for (int mf = 0; mf < 2; mf++)
        #pragma unroll
        for (int nf = 0; nf < 6; nf++) {
            int row = m0 + wm * 32 + mf * 16 + g;
            int col = wn * 48 + nf * 8 + tig * 2;
            float d0 = acc[mf][nf][0], d1 = acc[mf][nf][1];
            float d2 = acc[mf][nf][2], d3 = acc[mf][nf][3];
            *(float2*)(C + (size_t)row * CMID + col)       = make_float2(d0, d1);
            *(float2*)(C + (size_t)(row + 8) * CMID + col) = make_float2(d2, d3);
            int grp = col / 24;
            gs[grp]     += d0 + d1 + d2 + d3;
            gs[8 + grp] += d0*d0 + d1*d1 + d2*d2 + d3*d3;
        }
    __syncthreads();
    float* red = (float*)smem;
    #pragma unroll
    for (int i = 0; i < 16; i++) red[i * 512 + tid] = gs[i];
    __syncthreads();
    for (int off = 256; off > 0; off >>= 1) {
        if (tid < off) {
            #pragma unroll
            for (int i = 0; i < 16; i++) red[i * 512 + tid] += red[i * 512 + tid + off];
        }
        __syncthreads();
    }
    if (tid < 16) {
        int b = blockIdx.x >> 7, cta = blockIdx.x & 127;
        int grp = tid & 7;
        part[(tid >= 8 ? 4096 : 0) + (b * 8 + grp) * 128 + cta] = red[tid * 512];
    }
}

// ==================== GEMM2: 3-term fp16x3, reg-prefetch, GN1 affine+relu fused, GN2 stats ====================
// CTA 128x128, warps 2x4 (64x32), BK=32
#define G2_AH 0
#define G2_AL 10240
#define G2_BH 20480
#define G2_BL 30720
#define G2_AFF 40960
#define G2_SMEM (G2_AFF + 2 * CMID * 4)

__global__ void __launch_bounds__(256) gemm2_mma(
    const float* __restrict__ H,
    const __half* __restrict__ Bh, const __half* __restrict__ Bl,
    const float* __restrict__ a1, const float* __restrict__ b1,
    float* __restrict__ Out, float* __restrict__ part)
{
    extern __shared__ char smem[];
    const uint32_t sb = smem_u32(smem);
    const int tid = threadIdx.x, lane = tid & 31, wid = tid >> 5;
    const int wm = wid & 1, wn = wid >> 1;
    const int m0 = blockIdx.x * 128;
    const int bb = blockIdx.x >> 7;

    float* s_a = (float*)(smem + G2_AFF);
    float* s_b = s_a + CMID;
    for (int i = tid; i < CMID; i += 256) { s_a[i] = a1[bb * CMID + i]; s_b[i] = b1[bb * CMID + i]; }
    __syncthreads();

    const int arow = tid >> 1, akoff = (tid & 1) * 16;

    float acc[4][4][4];
    #pragma unroll
    for (int i = 0; i < 4; i++)
        #pragma unroll
        for (int j = 0; j < 4; j++)
            #pragma unroll
            for (int k = 0; k < 4; k++) acc[i][j][k] = 0.0f;

    uint4 aH[2], aL[2], bH[2], bL[2];
    auto loadG = [&](int it) {
        int kc0 = it * 32;
        const float* hrow = H + (size_t)(m0 + arow) * CMID + kc0 + akoff;
        uint32_t hq[8], lq[8];
        #pragma unroll
        for (int e = 0; e < 8; e++) {
            int c = kc0 + akoff + e * 2;
            float x = fmaxf(fmaf(hrow[e*2],   s_a[c],   s_b[c]),   0.0f);
            float y = fmaxf(fmaf(hrow[e*2+1], s_a[c+1], s_b[c+1]), 0.0f);
            split2(x, y, hq[e], lq[e]);
        }
        aH[0] = make_uint4(hq[0], hq[1], hq[2], hq[3]);
        aH[1] = make_uint4(hq[4], hq[5], hq[6], hq[7]);
        aL[0] = make_uint4(lq[0], lq[1], lq[2], lq[3]);
        aL[1] = make_uint4(lq[4], lq[5], lq[6], lq[7]);
        bH[0] = *(const uint4*)(Bh + (size_t)arow * CMID + kc0 + akoff);
        bH[1] = *(const uint4*)(Bh + (size_t)arow * CMID + kc0 + akoff + 8);
        bL[0] = *(const uint4*)(Bl + (size_t)arow * CMID + kc0 + akoff);
        bL[1] = *(const uint4*)(Bl + (size_t)arow * CMID + kc0 + akoff + 8);
    };
    auto storeS = [&]() {
        *(uint4*)(smem + G2_AH + arow * 80 + akoff * 2)      = aH[0];
        *(uint4*)(smem + G2_AH + arow * 80 + akoff * 2 + 16) = aH[1];
        *(uint4*)(smem + G2_AL + arow * 80 + akoff * 2)      = aL[0];
        *(uint4*)(smem + G2_AL + arow * 80 + akoff * 2 + 16) = aL[1];
        *(uint4*)(smem + G2_BH + arow * 80 + akoff * 2)      = bH[0];
        *(uint4*)(smem + G2_BH + arow * 80 + akoff * 2 + 16) = bH[1];
        *(uint4*)(smem + G2_BL + arow * 80 + akoff * 2)      = bL[0];
        *(uint4*)(smem + G2_BL + arow * 80 + akoff * 2 + 16) = bL[1];
    };

    const int lrow = lane & 15, lk = (lane >> 4) * 8;
    loadG(0);
    for (int it = 0; it < 6; it++) {
        storeS();
        __syncthreads();
        if (it < 5) loadG(it + 1);
        #pragma unroll
        for (int s = 0; s < 2; s++) {
            const int kc = s * 16;
            uint32_t fAh[4][4], fAl[4][4];
            #pragma unroll
            for (int mf = 0; mf < 4; mf++) {
                uint32_t off = (uint32_t)(((wm * 64 + mf * 16 + lrow) * 40 + kc + lk) * 2);
                LDSM4(fAh[mf][0], fAh[mf][1], fAh[mf][2], fAh[mf][3], sb + G2_AH + off);
                LDSM4(fAl[mf][0], fAl[mf][1], fAl[mf][2], fAl[mf][3], sb + G2_AL + off);
            }
            uint32_t fBh[4][2], fBl[4][2];
            #pragma unroll
            for (int q = 0; q < 2; q++) {
                uint32_t off = (uint32_t)(((wn * 32 + q * 16 + lrow) * 40 + kc + lk) * 2);
                uint32_t r0, r1, r2, r3;
                LDSM4(r0, r1, r2, r3, sb + G2_BH + off);
                fBh[q*2][0] = r0; fBh[q*2][1] = r2;
                fBh[q*2+1][0] = r1; fBh[q*2+1][1] = r3;
                LDSM4(r0, r1, r2, r3, sb + G2_BL + off);
                fBl[q*2][0] = r0; fBl[q*2][1] = r2;
                fBl[q*2+1][0] = r1; fBl[q*2+1][1] = r3;
            }
            #pragma unroll
            for (int mf = 0; mf < 4; mf++)
                #pragma unroll
                for (int nf = 0; nf < 4; nf++) {
                    MMA16816(acc[mf][nf], fAh[mf][0], fAh[mf][1], fAh[mf][2], fAh[mf][3],
                             fBh[nf][0], fBh[nf][1]);
                    MMA16816(acc[mf][nf], fAh[mf][0], fAh[mf][1], fAh[mf][2], fAh[mf][3],
                             fBl[nf][0], fBl[nf][1]);
                    MMA16816(acc[mf][nf], fAl[mf][0], fAl[mf][1], fAl[mf][2], fAl[mf][3],
                             fBh[nf][0], fBh[nf][1]);
                }
        }
        __syncthreads();
    }

    // epilogue: write Out + GN2 partial stats
    const int g = lane >> 2, tig = lane & 3;
    float gs[16];
    #pragma unroll
    for (int i = 0; i < 16; i++) gs[i] = 0.0f;
    #pragma unroll
    for (int mf = 0; mf < 4; mf++)
        #pragma unroll
        for (int nf = 0; nf < 4; nf++) {
            int row = m0 + wm * 64 + mf * 16 + g;
            int col = wn * 32 + nf * 8 + tig * 2;
            float d0 = acc[mf][nf][0], d1 = acc[mf][nf][1];
            float d2 = acc[mf][nf][2], d3 = acc[mf][nf][3];
            *(float2*)(Out + (size_t)row * COUT + col)       = make_float2(d0, d1);
            *(float2*)(Out + (size_t)(row + 8) * COUT + col) = make_float2(d2, d3);
            int grp = col >> 4;
            gs[grp]     += d0 + d1 + d2 + d3;
            gs[8 + grp] += d0*d0 + d1*d1 + d2*d2 + d3*d3;
        }
    __syncthreads();
    float* red = (float*)smem;
    #pragma unroll
    for (int i = 0; i < 16; i++) red[i * 256 + tid] = gs[i];
    __syncthreads();
    for (int off = 128; off > 0; off >>= 1) {
        if (tid < off) {
            #pragma unroll
            for (int i = 0; i < 16; i++) red[i * 256 + tid] += red[i * 256 + tid + off];
        }
        __syncthreads();
    }
    if (tid < 16) {
        int cta = blockIdx.x & 127;
        int grp = tid & 7;
        part[(tid >= 8 ? 4096 : 0) + (bb * 8 + grp) * 128 + cta] = red[tid * 256];
    }
}

// ==================== GN final ====================
template<int CPG>
__global__ void stats_final(
    const float* __restrict__ ps, const float* __restrict__ pss,
    const float* __restrict__ gamma, const float* __restrict__ beta,
    float* __restrict__ ac, float* __restrict__ bc, int Cdim)
{
    const int bg = blockIdx.x;
    const int b = bg >> 3, g = bg & 7;
    __shared__ float s_m, s_i;
    if (threadIdx.x == 0) {
        float s = 0.0f, ss = 0.0f;
        for (int i = 0; i < 128; i++) { s += ps[bg * 128 + i]; ss += pss[bg * 128 + i]; }
        float cnt = (float)NPTS * (float)CPG;
        float mu = s / cnt;
        float var = ss / cnt - mu * mu;
        s_m = mu; s_i = rsqrtf(var + EPS_GN);
    }
    __syncthreads();
    int ch = g * CPG + threadIdx.x;
    float a = gamma[ch] * s_i;
    ac[b * Cdim + ch] = a;
    bc[b * Cdim + ch] = beta[ch] - s_m * a;
}

// ==================== finalize ====================
__global__ void __launch_bounds__(256) finalize_kernel(
    float* __restrict__ out, const float* __restrict__ a, const float* __restrict__ bc)
{
    size_t i = (size_t)blockIdx.x * 256 + threadIdx.x;
    int c = (int)(i & 127);
    int b = (int)(i >> 21);
    float v = out[i];
    out[i] = fmaxf(fmaf(v, a[b * COUT + c], bc[b * COUT + c]), 0.0f);
}

// ==================== launch ====================
extern "C" void kernel_launch(void* const* d_in, const int* in_sizes, int n_in,
                              void* d_out, int out_size)
{
    const float* fine_xyz    = (const float*)d_in[0];
    const float* coarse_xyz  = (const float*)d_in[1];
    const float* fine_feat   = (const float*)d_in[2];
    const float* coarse_feat = (const float*)d_in[3];
    const float* w1          = (const float*)d_in[4];
    const float* g1_w        = (const float*)d_in[5];
    const float* g1_b        = (const float*)d_in[6];
    const float* w2          = (const float*)d_in[7];
    const float* g2_w        = (const float*)d_in[8];
    const float* g2_b        = (const float*)d_in[9];
    float* out = (float*)d_out;

    __half *chi, *w1h, *w2h, *w2l;
    float *h1, *wt, *part1, *part2, *a1, *b1, *a2, *b2;
    int* idx;
    cudaGetSymbolAddress((void**)&chi, g_comb_hi);
    cudaGetSymbolAddress((void**)&h1, g_h1);
    cudaGetSymbolAddress((void**)&idx, g_idx);
    cudaGetSymbolAddress((void**)&wt, g_wt);
    cudaGetSymbolAddress((void**)&w1h, g_w1h);
    cudaGetSymbolAddress((void**)&w2h, g_w2h);
    cudaGetSymbolAddress((void**)&w2l, g_w2l);
    cudaGetSymbolAddress((void**)&part1, g_part1);
    cudaGetSymbolAddress((void**)&part2, g_part2);
    cudaGetSymbolAddress((void**)&a1, g_a1);
    cudaGetSymbolAddress((void**)&b1, g_b1);
    cudaGetSymbolAddress((void**)&a2, g_a2);
    cudaGetSymbolAddress((void**)&b2, g_b2);

    cudaFuncSetAttribute(gemm1_mma, cudaFuncAttributeMaxDynamicSharedMemorySize, G1_SMEM);
    cudaFuncSetAttribute(gemm2_mma, cudaFuncAttributeMaxDynamicSharedMemorySize, G2_SMEM);

    knn_kernel<<<dim3(NPTS / 128, BATCH), 128>>>(fine_xyz, coarse_xyz, idx, wt);
    prep_weights<<<(CMID * CIN + COUT * CMID + 255) / 256, 256>>>(w1, w2, w1h, w2h, w2l);
    interp_kernel<<<BN_TOTAL / 8, 256>>>(fine_feat, coarse_feat, idx, wt, chi);
    gemm1_mma<<<BN_TOTAL / 128, 512, G1_SMEM>>>(chi, w1h, h1, part1);
    stats_final<CMID / GROUPS><<<BATCH * GROUPS, CMID / GROUPS>>>(part1, part1 + 4096, g1_w, g1_b, a1, b1, CMID);
    gemm2_mma<<<BN_TOTAL / 128, 256, G2_SMEM>>>(h1, w2h, w2l, a1, b1, out, part2);
    stats_final<COUT / GROUPS><<<BATCH * GROUPS, COUT / GROUPS>>>(part2, part2 + 4096, g2_w, g2_b, a2, b2, COUT);
    finalize_kernel<<<(BN_TOTAL * COUT) / 256, 256>>>(out, a2, b2);
}

// round 10
// speedup vs baseline: 1.5063x; 1.1363x over previous
#include <cuda_runtime.h>
#include <cuda_fp16.h>
#include <cstdint>
#include <cstddef>

// Problem constants
#define BATCH 4
#define NPTS  16384
#define SPTS  4096
#define CF    128
#define CC    256
#define CIN   384
#define CMID  192
#define COUT  128
#define GROUPS 8
#define EPS_GN 1e-5f
#define EPS_D  1e-8f
#define BN_TOTAL (BATCH * NPTS)   // 65536
#define CTAS_PER_BATCH 128

// -------------------- scratch (device globals; no allocation) --------------------
__device__ __align__(16) __half g_comb_hi[(size_t)BN_TOTAL * CIN];
__device__ __align__(16) float  g_h1[(size_t)BN_TOTAL * CMID];
__device__ int   g_idx[(size_t)BN_TOTAL * 3];
__device__ float g_wt[(size_t)BN_TOTAL * 3];
__device__ __align__(16) __half g_w1h[CMID * CIN];
__device__ __align__(16) __half g_w2h[COUT * CMID];
__device__ float g_part1[2 * 32 * CTAS_PER_BATCH];
__device__ float g_part2[2 * 32 * CTAS_PER_BATCH];
__device__ float g_a1[BATCH * CMID], g_b1[BATCH * CMID];
__device__ float g_a2[BATCH * COUT], g_b2[BATCH * COUT];

// ==================== helpers ====================
__device__ __forceinline__ uint32_t smem_u32(const void* p) {
    uint32_t a;
    asm("{ .reg .u64 t; cvta.to.shared.u64 t, %1; cvt.u32.u64 %0, t; }" : "=r"(a) : "l"(p));
    return a;
}
#define LDSM4(r0, r1, r2, r3, addr) \
    asm volatile("ldmatrix.sync.aligned.m8n8.x4.shared.b16 {%0,%1,%2,%3}, [%4];" \
        : "=r"(r0), "=r"(r1), "=r"(r2), "=r"(r3) : "r"(addr))
#define MMA16816(d, a0, a1, a2, a3, b0, b1) \
    asm volatile("mma.sync.aligned.m16n8k16.row.col.f32.f16.f16.f32 " \
        "{%0,%1,%2,%3},{%4,%5,%6,%7},{%8,%9},{%0,%1,%2,%3};" \
        : "+f"((d)[0]), "+f"((d)[1]), "+f"((d)[2]), "+f"((d)[3]) \
        : "r"(a0), "r"(a1), "r"(a2), "r"(a3), "r"(b0), "r"(b1))
#define CP16(dst, src) \
    asm volatile("cp.async.cg.shared.global [%0], [%1], 16;" :: "r"(dst), "l"(src))
#define CP_COMMIT() asm volatile("cp.async.commit_group;" ::: "memory")
#define CP_WAIT1()  asm volatile("cp.async.wait_group 1;" ::: "memory")

__device__ __forceinline__ uint32_t pack2(float x, float y) {
    __half hx = __float2half_rn(x), hy = __float2half_rn(y);
    return ((uint32_t)__half_as_ushort(hy) << 16) | __half_as_ushort(hx);
}

// ==================== Kernel 1: kNN (K=3) + IDW weights (1 query/thread) ====================
#define KNN_CHUNK 2048
__global__ void __launch_bounds__(128) knn_kernel(
    const float* __restrict__ fxyz, const float* __restrict__ cxyz,
    int* __restrict__ oidx, float* __restrict__ owt)
{
    __shared__ float4 cs[KNN_CHUNK];
    const int b = blockIdx.y;
    const int n = blockIdx.x * 128 + threadIdx.x;
    const float* fp = fxyz + ((size_t)b * NPTS + n) * 3;
    const float qx = fp[0], qy = fp[1], qz = fp[2];
    const float qn = qx*qx + qy*qy + qz*qz;

    float s0 = 3.4e38f, s1 = 3.4e38f, s2 = 3.4e38f;
    int   i0 = 0, i1 = 0, i2 = 0;

    for (int c0 = 0; c0 < SPTS; c0 += KNN_CHUNK) {
        __syncthreads();
        for (int j = threadIdx.x; j < KNN_CHUNK; j += 128) {
            const float* cp = cxyz + ((size_t)b * SPTS + c0 + j) * 3;
            float x = cp[0], y = cp[1], z = cp[2];
            cs[j] = make_float4(x, y, z, x*x + y*y + z*z);
        }
        __syncthreads();
        #pragma unroll 8
        for (int j = 0; j < KNN_CHUNK; j++) {
            float4 c = cs[j];
            float dot = qx*c.x + qy*c.y + qz*c.z;
            float score = fmaf(-2.0f, dot, qn + c.w);   // reference ranking formula
            if (score < s2) {
                int idx = c0 + j;
                if (score < s1) {
                    s2 = s1; i2 = i1;
                    if (score < s0) { s1 = s0; i1 = i0; s0 = score; i0 = idx; }
                    else            { s1 = score; i1 = idx; }
                } else { s2 = score; i2 = idx; }
            }
        }
    }
    int ii[3] = { i0, i1, i2 };
    float w[3], wsum = 0.0f;
    #pragma unroll
    for (int k = 0; k < 3; k++) {
        const float* cp = cxyz + ((size_t)b * SPTS + ii[k]) * 3;
        float dx = qx - cp[0], dy = qy - cp[1], dz = qz - cp[2];
        float d2 = fmaxf(dx*dx + dy*dy + dz*dz, EPS_D);
        w[k] = 1.0f / d2; wsum += w[k];
    }
    float inv = 1.0f / wsum;
    size_t base = ((size_t)b * NPTS + n) * 3;
    #pragma unroll
    for (int k = 0; k < 3; k++) { oidx[base + k] = ii[k]; owt[base + k] = w[k] * inv; }
}

// ==================== Kernel 2: weights -> fp16 (hi only) ====================
__global__ void prep_weights(const float* __restrict__ w1, const float* __restrict__ w2,
                             __half* w1h, __half* w2h)
{
    int i = blockIdx.x * 256 + threadIdx.x;
    if (i < CMID * CIN) w1h[i] = __float2half_rn(w1[i]);
    int j = i - CMID * CIN;
    if (j >= 0 && j < COUT * CMID) w2h[j] = __float2half_rn(w2[j]);
}

// ==================== Kernel 3: interp + concat -> fp16 (hi only) ====================
__global__ void __launch_bounds__(256) interp_kernel(
    const float* __restrict__ ffeat, const float* __restrict__ cfeat,
    const int* __restrict__ idx, const float* __restrict__ wt,
    __half* __restrict__ chi)
{
    const int gwarp = (blockIdx.x * 256 + threadIdx.x) >> 5;
    const int lane  = threadIdx.x & 31;
    const size_t p  = (size_t)gwarp;
    const int b     = (int)(p >> 14);

    const int*   ip = idx + p * 3;
    const float* wp = wt  + p * 3;
    int   j0 = ip[0], j1 = ip[1], j2 = ip[2];
    float w0 = wp[0], w1v = wp[1], w2v = wp[2];

    char* hbase = (char*)(chi + p * CIN);
    const float4* f4 = (const float4*)(ffeat + p * CF);
    {
        float4 v = f4[lane];
        *(uint2*)(hbase + lane * 8) = make_uint2(pack2(v.x, v.y), pack2(v.z, v.w));
    }
    const float4* c0 = (const float4*)(cfeat + ((size_t)b * SPTS + j0) * CC);
    const float4* c1 = (const float4*)(cfeat + ((size_t)b * SPTS + j1) * CC);
    const float4* c2 = (const float4*)(cfeat + ((size_t)b * SPTS + j2) * CC);
    #pragma unroll
    for (int t = 0; t < 2; t++) {
        int c = t * 32 + lane;
        float4 A = c0[c], B = c1[c], Cv = c2[c];
        float4 r;
        r.x = w0*A.x + w1v*B.x + w2v*Cv.x;
        r.y = w0*A.y + w1v*B.y + w2v*Cv.y;
        r.z = w0*A.z + w1v*B.z + w2v*Cv.z;
        r.w = w0*A.w + w1v*B.w + w2v*Cv.w;
        *(uint2*)(hbase + 256 + c * 8) = make_uint2(pack2(r.x, r.y), pack2(r.z, r.w));
    }
}

// ==================== GEMM1: single-term fp16, 512 thr, 3-stage cp.async + GN1 stats ====================
// CTA tile 128x192, warp grid 4x4 (warp tile 32x48), BK=32
#define G1_AH 0
#define G1_BH 10240
#define G1_STAGE 25600
#define G1_SMEM (3 * G1_STAGE)   // 76800

__global__ void __launch_bounds__(512) gemm1_mma(
    const __half* __restrict__ Ah, const __half* __restrict__ Bh,
    float* __restrict__ C, float* __restrict__ part)
{
    extern __shared__ char smem[];
    const uint32_t sb = smem_u32(smem);
    const int tid = threadIdx.x, lane = tid & 31, wid = tid >> 5;
    const int wm = wid & 3, wn = wid >> 2;          // warp grid 4 x 4
    const int m0 = blockIdx.x * 128;

    auto issue = [&](int it, int buf) {
        const int kc0 = it * 32;
        const uint32_t base = sb + buf * G1_STAGE;
        {   // A: 512 CP16, 1 per thread
            int row = tid >> 2, ko = (tid & 3) * 8;
            CP16(base + G1_AH + row * 80 + ko * 2, Ah + (size_t)(m0 + row) * CIN + kc0 + ko);
        }
        #pragma unroll
        for (int q = 0; q < 2; q++) {    // B: 768 CP16
            int i = q * 512 + tid;
            if (i < 768) {
                int row = i >> 2, ko = (i & 3) * 8;
                CP16(base + G1_BH + row * 80 + ko * 2, Bh + (size_t)row * CIN + kc0 + ko);
            }
        }
    };

    float acc[2][6][4];
    #pragma unroll
    for (int i = 0; i < 2; i++)
        #pragma unroll
        for (int j = 0; j < 6; j++)
            #pragma unroll
            for (int k = 0; k < 4; k++) acc[i][j][k] = 0.0f;

    issue(0, 0); CP_COMMIT();
    issue(1, 1); CP_COMMIT();

    const int lrow = lane & 15, lk = (lane >> 4) * 8;
    for (int it = 0; it < 12; it++) {
        CP_WAIT1();
        __syncthreads();
        if (it + 2 < 12) issue(it + 2, (it + 2) % 3);
        CP_COMMIT();                 // empty group at drain keeps the count aligned
        const uint32_t bufb = sb + (it % 3) * G1_STAGE;
        #pragma unroll
        for (int s = 0; s < 2; s++) {
            const int kc = s * 16;
            uint32_t fA[2][4];
            #pragma unroll
            for (int mf = 0; mf < 2; mf++) {
                uint32_t off = (uint32_t)(((wm * 32 + mf * 16 + lrow) * 40 + kc + lk) * 2);
                LDSM4(fA[mf][0], fA[mf][1], fA[mf][2], fA[mf][3], bufb + G1_AH + off);
            }
            uint32_t fB[6][2];
            #pragma unroll
            for (int q = 0; q < 3; q++) {
                uint32_t off = (uint32_t)(((wn * 48 + q * 16 + lrow) * 40 + kc + lk) * 2);
                uint32_t r0, r1, r2, r3;
                LDSM4(r0, r1, r2, r3, bufb + G1_BH + off);
                fB[q*2][0] = r0; fB[q*2][1] = r2;
                fB[q*2+1][0] = r1; fB[q*2+1][1] = r3;
            }
            #pragma unroll
            for (int mf = 0; mf < 2; mf++)
                #pragma unroll
                for (int nf = 0; nf < 6; nf++)
                    MMA16816(acc[mf][nf], fA[mf][0], fA[mf][1], fA[mf][2], fA[mf][3],
                             fB[nf][0], fB[nf][1]);
        }
        __syncthreads();
    }

    // epilogue: write C + GN1 partial stats from accumulators
    const int g = lane >> 2, tig = lane & 3;
    float gs[16];
    #pragma unroll
    for (int i = 0; i < 16; i++) gs[i] = 0.0f;
    #pragma unroll
    for (int mf = 0; mf < 2; mf++)
        #pragma unroll
        for (int nf = 0; nf < 6; nf++) {
            int row = m0 + wm * 32 + mf * 16 + g;
            int col = wn * 48 + nf * 8 + tig * 2;
            float d0 = acc[mf][nf][0], d1 = acc[mf][nf][1];
            float d2 = acc[mf][nf][2], d3 = acc[mf][nf][3];
            *(float2*)(C + (size_t)row * CMID + col)       = make_float2(d0, d1);
            *(float2*)(C + (size_t)(row + 8) * CMID + col) = make_float2(d2, d3);
            int grp = col / 24;
            gs[grp]     += d0 + d1 + d2 + d3;
            gs[8 + grp] += d0*d0 + d1*d1 + d2*d2 + d3*d3;
        }
    __syncthreads();
    float* red = (float*)smem;
    #pragma unroll
    for (int i = 0; i < 16; i++) red[i * 512 + tid] = gs[i];
    __syncthreads();
    for (int off = 256; off > 0; off >>= 1) {
        if (tid < off) {
            #pragma unroll
            for (int i = 0; i < 16; i++) red[i * 512 + tid] += red[i * 512 + tid + off];
        }
        __syncthreads();
    }
    if (tid < 16) {
        int b = blockIdx.x >> 7, cta = blockIdx.x & 127;
        int grp = tid & 7;
        part[(tid >= 8 ? 4096 : 0) + (b * 8 + grp) * 128 + cta] = red[tid * 512];
    }
}

// ==================== GEMM2: single-term fp16, 512 thr, 3-stage cp.async ====================
// out[65536,128] = relu(gn1(h1))[65536,192] @ w2[128,192]^T
// CTA 128x128, warp grid 4x4 (warp tile 32x32), BK=32, 6 K-iters
// stage = A32 (128x40 fp32 = 20480) + B (128x40 half = 10240) = 30720
#define G2_A32 0
#define G2_B   20480
#define G2_STAGE 30720
#define G2_CAH (3 * G2_STAGE)            // 92160: converted fp16 A (single buffer)
#define G2_AFF (G2_CAH + 10240)          // 102400
#define G2_SMEM (G2_AFF + 2 * CMID * 4)  // 103936

__global__ void __launch_bounds__(512) gemm2_mma(
    const float* __restrict__ H, const __half* __restrict__ Bh,
    const float* __restrict__ a1, const float* __restrict__ b1,
    float* __restrict__ Out, float* __restrict__ part)
{
    extern __shared__ char smem[];
    const uint32_t sb = smem_u32(smem);
    const int tid = threadIdx.x, lane = tid & 31, wid = tid >> 5;
    const int wm = wid & 3, wn = wid >> 2;           // warp grid 4 x 4
    const int m0 = blockIdx.x * 128;
    const int bb = blockIdx.x >> 7;

    float* s_a = (float*)(smem + G2_AFF);
    float* s_b = s_a + CMID;
    for (int i = tid; i < CMID; i += 512) { s_a[i] = a1[bb * CMID + i]; s_b[i] = b1[bb * CMID + i]; }

    auto issue = [&](int it, int buf) {
        const int kc0 = it * 32;
        const uint32_t base = sb + buf * G2_STAGE;
        #pragma unroll
        for (int u = 0; u < 2; u++) {     // A32: 1024 CP16 (128 rows x 8 groups of 4 floats)
            int i = u * 512 + tid;
            int row = i >> 3, ko = (i & 7) * 4;
            CP16(base + G2_A32 + row * 160 + ko * 4, H + (size_t)(m0 + row) * CMID + kc0 + ko);
        }
        {   // B: 512 CP16 (128 rows x 4 groups of 8 halves)
            int row = tid >> 2, ko = (tid & 3) * 8;
            CP16(base + G2_B + row * 80 + ko * 2, Bh + (size_t)row * CMID + kc0 + ko);
        }
    };

    float acc[2][4][4];
    #pragma unroll
    for (int i = 0; i < 2; i++)
        #pragma unroll
        for (int j = 0; j < 4; j++)
            #pragma unroll
            for (int k = 0; k < 4; k++) acc[i][j][k] = 0.0f;

    __syncthreads();   // affine coefs visible
    issue(0, 0); CP_COMMIT();
    issue(1, 1); CP_COMMIT();

    const int crow = tid >> 2, cko = (tid & 3) * 8;  // convert: 8 floats/thread
    const int lrow = lane & 15, lk = (lane >> 4) * 8;
    for (int it = 0; it < 6; it++) {
        CP_WAIT1();
        __syncthreads();
        if (it + 2 < 6) issue(it + 2, (it + 2) % 3);
        CP_COMMIT();
        const uint32_t bufb = sb + (it % 3) * G2_STAGE;
        // convert: fp32 + GN1 affine + relu -> fp16 in convert buffer
        {
            const int kc0 = it * 32;
            const float* rowp = (const float*)(smem + (it % 3) * G2_STAGE + G2_A32) + crow * 40 + cko;
            uint32_t hq[4];
            #pragma unroll
            for (int e = 0; e < 4; e++) {
                int c = kc0 + cko + e * 2;
                float x = fmaxf(fmaf(rowp[e*2],   s_a[c],   s_b[c]),   0.0f);
                float y = fmaxf(fmaf(rowp[e*2+1], s_a[c+1], s_b[c+1]), 0.0f);
                hq[e] = pack2(x, y);
            }
            *(uint4*)(smem + G2_CAH + crow * 80 + cko * 2) = make_uint4(hq[0], hq[1], hq[2], hq[3]);
        }
        __syncthreads();
        #pragma unroll
        for (int s = 0; s < 2; s++) {
            const int kc = s * 16;
            uint32_t fA[2][4];
            #pragma unroll
            for (int mf = 0; mf < 2; mf++) {
                uint32_t off = (uint32_t)(((wm * 32 + mf * 16 + lrow) * 40 + kc + lk) * 2);
                LDSM4(fA[mf][0], fA[mf][1], fA[mf][2], fA[mf][3], sb + G2_CAH + off);
            }
            uint32_t fB[4][2];
            #pragma unroll
            for (int q = 0; q < 2; q++) {
                uint32_t off = (uint32_t)(((wn * 32 + q * 16 + lrow) * 40 + kc + lk) * 2);
                uint32_t r0, r1, r2, r3;
                LDSM4(r0, r1, r2, r3, bufb + G2_B + off);
                fB[q*2][0] = r0; fB[q*2][1] = r2;
                fB[q*2+1][0] = r1; fB[q*2+1][1] = r3;
            }
            #pragma unroll
            for (int mf = 0; mf < 2; mf++)
                #pragma unroll
                for (int nf = 0; nf < 4; nf++)
                    MMA16816(acc[mf][nf], fA[mf][0], fA[mf][1], fA[mf][2], fA[mf][3],
                             fB[nf][0], fB[nf][1]);
        }
        __syncthreads();
    }

    // epilogue: write Out + GN2 partial stats
    const int g = lane >> 2, tig = lane & 3;
    float gs[16];
    #pragma unroll
    for (int i = 0; i < 16; i++) gs[i] = 0.0f;
    #pragma unroll
    for (int mf = 0; mf < 2; mf++)
        #pragma unroll
        for (int nf = 0; nf < 4; nf++) {
            int row = m0 + wm * 32 + mf * 16 + g;
            int col = wn * 32 + nf * 8 + tig * 2;
            float d0 = acc[mf][nf][0], d1 = acc[mf][nf][1];
            float d2 = acc[mf][nf][2], d3 = acc[mf][nf][3];
            *(float2*)(Out + (size_t)row * COUT + col)       = make_float2(d0, d1);
            *(float2*)(Out + (size_t)(row + 8) * COUT + col) = make_float2(d2, d3);
            int grp = col >> 4;
            gs[grp]     += d0 + d1 + d2 + d3;
            gs[8 + grp] += d0*d0 + d1*d1 + d2*d2 + d3*d3;
        }
    __syncthreads();
    float* red = (float*)smem;
    #pragma unroll
    for (int i = 0; i < 16; i++) red[i * 512 + tid] = gs[i];
    __syncthreads();
    for (int off = 256; off > 0; off >>= 1) {
        if (tid < off) {
            #pragma unroll
            for (int i = 0; i < 16; i++) red[i * 512 + tid] += red[i * 512 + tid + off];
        }
        __syncthreads();
    }
    if (tid < 16) {
        int cta = blockIdx.x & 127;
        int grp = tid & 7;
        part[(tid >= 8 ? 4096 : 0) + (bb * 8 + grp) * 128 + cta] = red[tid * 512];
    }
}

// ==================== GN final ====================
template<int CPG>
__global__ void stats_final(
    const float* __restrict__ ps, const float* __restrict__ pss,
    const float* __restrict__ gamma, const float* __restrict__ beta,
    float* __restrict__ ac, float* __restrict__ bc, int Cdim)
{
    const int bg = blockIdx.x;
    const int b = bg >> 3, g = bg & 7;
    __shared__ float s_m, s_i;
    if (threadIdx.x == 0) {
        float s = 0.0f, ss = 0.0f;
        for (int i = 0; i < 128; i++) { s += ps[bg * 128 + i]; ss += pss[bg * 128 + i]; }
        float cnt = (float)NPTS * (float)CPG;
        float mu = s / cnt;
        float var = ss / cnt - mu * mu;
        s_m = mu; s_i = rsqrtf(var + EPS_GN);
    }
    __syncthreads();
    int ch = g * CPG + threadIdx.x;
    float a = gamma[ch] * s_i;
    ac[b * Cdim + ch] = a;
    bc[b * Cdim + ch] = beta[ch] - s_m * a;
}

// ==================== finalize ====================
__global__ void __launch_bounds__(256) finalize_kernel(
    float* __restrict__ out, const float* __restrict__ a, const float* __restrict__ bc)
{
    size_t i = (size_t)blockIdx.x * 256 + threadIdx.x;
    int c = (int)(i & 127);
    int b = (int)(i >> 21);
    float v = out[i];
    out[i] = fmaxf(fmaf(v, a[b * COUT + c], bc[b * COUT + c]), 0.0f);
}

// ==================== launch ====================
extern "C" void kernel_launch(void* const* d_in, const int* in_sizes, int n_in,
                              void* d_out, int out_size)
{
    const float* fine_xyz    = (const float*)d_in[0];
    const float* coarse_xyz  = (const float*)d_in[1];
    const float* fine_feat   = (const float*)d_in[2];
    const float* coarse_feat = (const float*)d_in[3];
    const float* w1          = (const float*)d_in[4];
    const float* g1_w        = (const float*)d_in[5];
    const float* g1_b        = (const float*)d_in[6];
    const float* w2          = (const float*)d_in[7];
    const float* g2_w        = (const float*)d_in[8];
    const float* g2_b        = (const float*)d_in[9];
    float* out = (float*)d_out;

    __half *chi, *w1h, *w2h;
    float *h1, *wt, *part1, *part2, *a1, *b1, *a2, *b2;
    int* idx;
    cudaGetSymbolAddress((void**)&chi, g_comb_hi);
    cudaGetSymbolAddress((void**)&h1, g_h1);
    cudaGetSymbolAddress((void**)&idx, g_idx);
    cudaGetSymbolAddress((void**)&wt, g_wt);
    cudaGetSymbolAddress((void**)&w1h, g_w1h);
    cudaGetSymbolAddress((void**)&w2h, g_w2h);
    cudaGetSymbolAddress((void**)&part1, g_part1);
    cudaGetSymbolAddress((void**)&part2, g_part2);
    cudaGetSymbolAddress((void**)&a1, g_a1);
    cudaGetSymbolAddress((void**)&b1, g_b1);
    cudaGetSymbolAddress((void**)&a2, g_a2);
    cudaGetSymbolAddress((void**)&b2, g_b2);

    cudaFuncSetAttribute(gemm1_mma, cudaFuncAttributeMaxDynamicSharedMemorySize, G1_SMEM);
    cudaFuncSetAttribute(gemm2_mma, cudaFuncAttributeMaxDynamicSharedMemorySize, G2_SMEM);

    knn_kernel<<<dim3(NPTS / 128, BATCH), 128>>>(fine_xyz, coarse_xyz, idx, wt);
    prep_weights<<<(CMID * CIN + COUT * CMID + 255) / 256, 256>>>(w1, w2, w1h, w2h);
    interp_kernel<<<BN_TOTAL / 8, 256>>>(fine_feat, coarse_feat, idx, wt, chi);
    gemm1_mma<<<BN_TOTAL / 128, 512, G1_SMEM>>>(chi, w1h, h1, part1);
    stats_final<CMID / GROUPS><<<BATCH * GROUPS, CMID / GROUPS>>>(part1, part1 + 4096, g1_w, g1_b, a1, b1, CMID);
    gemm2_mma<<<BN_TOTAL / 128, 512, G2_SMEM>>>(h1, w2h, a1, b1, out, part2);
    stats_final<COUT / GROUPS><<<BATCH * GROUPS, COUT / GROUPS>>>(part2, part2 + 4096, g2_w, g2_b, a2, b2, COUT);
    finalize_kernel<<<(BN_TOTAL * COUT) / 256, 256>>>(out, a2, b2);
}

// round 12
// speedup vs baseline: 1.5241x; 1.0118x over previous
#include <cuda_runtime.h>
#include <cuda_fp16.h>
#include <cstdint>
#include <cstddef>

// Problem constants
#define BATCH 4
#define NPTS  16384
#define SPTS  4096
#define CF    128
#define CC    256
#define CIN   384
#define CMID  192
#define COUT  128
#define GROUPS 8
#define EPS_GN 1e-5f
#define EPS_D  1e-8f
#define BN_TOTAL (BATCH * NPTS)   // 65536
#define CTAS_PER_BATCH 128

// -------------------- scratch (device globals; no allocation) --------------------
__device__ __align__(16) float  g_h1[(size_t)BN_TOTAL * CMID];
__device__ int   g_idx[(size_t)BN_TOTAL * 3];
__device__ float g_wt[(size_t)BN_TOTAL * 3];
__device__ __align__(16) __half g_w1h[CMID * CIN];
__device__ __align__(16) __half g_w2h[COUT * CMID];
__device__ float g_part1[2 * 32 * CTAS_PER_BATCH];
__device__ float g_part2[2 * 32 * CTAS_PER_BATCH];
__device__ float g_a1[BATCH * CMID], g_b1[BATCH * CMID];
__device__ float g_a2[BATCH * COUT], g_b2[BATCH * COUT];

// ==================== helpers ====================
__device__ __forceinline__ uint32_t smem_u32(const void* p) {
    uint32_t a;
    asm("{ .reg .u64 t; cvta.to.shared.u64 t, %1; cvt.u32.u64 %0, t; }" : "=r"(a) : "l"(p));
    return a;
}
#define LDSM4(r0, r1, r2, r3, addr) \
    asm volatile("ldmatrix.sync.aligned.m8n8.x4.shared.b16 {%0,%1,%2,%3}, [%4];" \
        : "=r"(r0), "=r"(r1), "=r"(r2), "=r"(r3) : "r"(addr))
#define MMA16816(d, a0, a1, a2, a3, b0, b1) \
    asm volatile("mma.sync.aligned.m16n8k16.row.col.f32.f16.f16.f32 " \
        "{%0,%1,%2,%3},{%4,%5,%6,%7},{%8,%9},{%0,%1,%2,%3};" \
        : "+f"((d)[0]), "+f"((d)[1]), "+f"((d)[2]), "+f"((d)[3]) \
        : "r"(a0), "r"(a1), "r"(a2), "r"(a3), "r"(b0), "r"(b1))
#define CP16(dst, src) \
    asm volatile("cp.async.cg.shared.global [%0], [%1], 16;" :: "r"(dst), "l"(src))
#define CP_COMMIT() asm volatile("cp.async.commit_group;" ::: "memory")
#define CP_WAIT1()  asm volatile("cp.async.wait_group 1;" ::: "memory")

__device__ __forceinline__ uint32_t pack2(float x, float y) {
    __half hx = __float2half_rn(x), hy = __float2half_rn(y);
    return ((uint32_t)__half_as_ushort(hy) << 16) | __half_as_ushort(hx);
}

// ==================== Kernel 1: kNN (K=3) + IDW weights ====================
// candidates staged as (-2x, -2y, -2z, ||c||^2): score = fma chain of 3
#define KNN_CHUNK 2048
__global__ void __launch_bounds__(128) knn_kernel(
    const float* __restrict__ fxyz, const float* __restrict__ cxyz,
    int* __restrict__ oidx, float* __restrict__ owt)
{
    __shared__ float4 cs[KNN_CHUNK];
    const int b = blockIdx.y;
    const int n = blockIdx.x * 128 + threadIdx.x;
    const float* fp = fxyz + ((size_t)b * NPTS + n) * 3;
    const float qx = fp[0], qy = fp[1], qz = fp[2];

    float s0 = 3.4e38f, s1 = 3.4e38f, s2 = 3.4e38f;
    int   i0 = 0, i1 = 0, i2 = 0;

    for (int c0 = 0; c0 < SPTS; c0 += KNN_CHUNK) {
        __syncthreads();
        for (int j = threadIdx.x; j < KNN_CHUNK; j += 128) {
            const float* cp = cxyz + ((size_t)b * SPTS + c0 + j) * 3;
            float x = cp[0], y = cp[1], z = cp[2];
            cs[j] = make_float4(-2.0f * x, -2.0f * y, -2.0f * z, x*x + y*y + z*z);
        }
        __syncthreads();
        // score = ||c||^2 - 2 q.c  (reference score minus per-thread const ||q||^2:
        //  identical ordering)
        #pragma unroll 8
        for (int j = 0; j < KNN_CHUNK; j++) {
            float4 c = cs[j];
            float score = fmaf(qx, c.x, fmaf(qy, c.y, fmaf(qz, c.z, c.w)));
            if (score < s2) {
                int idx = c0 + j;
                if (score < s1) {
                    s2 = s1; i2 = i1;
                    if (score < s0) { s1 = s0; i1 = i0; s0 = score; i0 = idx; }
                    else            { s1 = score; i1 = idx; }
                } else { s2 = score; i2 = idx; }
            }
        }
    }
    int ii[3] = { i0, i1, i2 };
    float w[3], wsum = 0.0f;
    #pragma unroll
    for (int k = 0; k < 3; k++) {
        const float* cp = cxyz + ((size_t)b * SPTS + ii[k]) * 3;
        float dx = qx - cp[0], dy = qy - cp[1], dz = qz - cp[2];
        float d2 = fmaxf(dx*dx + dy*dy + dz*dz, EPS_D);
        w[k] = 1.0f / d2; wsum += w[k];
    }
    float inv = 1.0f / wsum;
    size_t base = ((size_t)b * NPTS + n) * 3;
    #pragma unroll
    for (int k = 0; k < 3; k++) { oidx[base + k] = ii[k]; owt[base + k] = w[k] * inv; }
}

// ==================== Kernel 2: weights -> fp16 (hi only) ====================
__global__ void prep_weights(const float* __restrict__ w1, const float* __restrict__ w2,
                             __half* w1h, __half* w2h)
{
    int i = blockIdx.x * 256 + threadIdx.x;
    if (i < CMID * CIN) w1h[i] = __float2half_rn(w1[i]);
    int j = i - CMID * CIN;
    if (j >= 0 && j < COUT * CMID) w2h[j] = __float2half_rn(w2[j]);
}

// ==================== GEMM1 (fused interp): 512 thr, 2-stage cp.async + GN1 stats ====================
// h1[65536,192] = concat(fine_feat, interp(coarse_feat)) @ w1^T
// CTA 128x192, warp grid 4x4 (32x48), BK=32, 12 K-chunks.
// Chunks 0-3: A = fine_feat fp32. Chunks 4-11: A = sum_k w_k * cfeat[idx_k] (gathered).
// Stage: 3 raw fp32 A buffers (128x40 fl = 20480 ea) + B (192x40 h = 15360) = 76800; 2 stages.
#define F_SA0 0
#define F_SA1 20480
#define F_SA2 40960
#define F_SB  61440
#define F_STAGE 76800
#define F_CONV (2 * F_STAGE)           // 153600: converted fp16 A (128x80)
#define F_IDX  (F_CONV + 10240)        // 163840: int idx3[384]
#define F_WT   (F_IDX + 1536)          // 165376: float wt3[384]
#define F_SMEM (F_WT + 1536)           // 166912

__global__ void __launch_bounds__(512) gemm1_fused(
    const float* __restrict__ ffeat, const float* __restrict__ cfeat,
    const int* __restrict__ idx, const float* __restrict__ wt,
    const __half* __restrict__ Bw,
    float* __restrict__ C, float* __restrict__ part)
{
    extern __shared__ char smem[];
    const uint32_t sb = smem_u32(smem);
    const int tid = threadIdx.x, lane = tid & 31, wid = tid >> 5;
    const int wm = wid & 3, wn = wid >> 2;          // warp grid 4 x 4
    const int m0 = blockIdx.x * 128;
    const int bb = blockIdx.x >> 7;

    int*   s_idx = (int*)(smem + F_IDX);
    float* s_wt  = (float*)(smem + F_WT);
    if (tid < 384) {
        int row = tid / 3, k = tid - row * 3;
        s_idx[tid] = idx[((size_t)(m0 + row)) * 3 + k];
        s_wt[tid]  = wt[((size_t)(m0 + row)) * 3 + k];
    }
    __syncthreads();

    auto issue = [&](int it, int buf) {
        const uint32_t base = sb + buf * F_STAGE;
        if (it < 4) {
            const int kc0 = it * 32;
            #pragma unroll
            for (int u = 0; u < 2; u++) {        // 1024 CP16: 128 rows x 8 chunks of 16B
                int i = u * 512 + tid;
                int row = i >> 3, ch = i & 7;
                CP16(base + F_SA0 + row * 160 + ch * 16,
                     ffeat + (size_t)(m0 + row) * CF + kc0 + ch * 4);
            }
        } else {
            const int cc0 = it * 32 - 128;
            #pragma unroll
            for (int q = 0; q < 3; q++) {        // 3 x 1024 CP16 gathered neighbor rows
                #pragma unroll
                for (int u = 0; u < 2; u++) {
                    int i = u * 512 + tid;
                    int row = i >> 3, ch = i & 7;
                    int j = s_idx[row * 3 + q];
                    CP16(base + F_SA0 + q * 20480 + row * 160 + ch * 16,
                         cfeat + ((size_t)bb * SPTS + j) * CC + cc0 + ch * 4);
                }
            }
        }
        {   // B: 768 CP16 (192 rows x 4 chunks of 8 halves)
            const int kc0 = it * 32;
            #pragma unroll
            for (int q = 0; q < 2; q++) {
                int i = q * 512 + tid;
                if (i < 768) {
                    int row = i >> 2, ko = (i & 3) * 8;
                    CP16(base + F_SB + row * 80 + ko * 2, Bw + (size_t)row * CIN + kc0 + ko);
                }
            }
        }
    };

    float acc[2][6][4];
    #pragma unroll
    for (int i = 0; i < 2; i++)
        #pragma unroll
        for (int j = 0; j < 6; j++)
            #pragma unroll
            for (int k = 0; k < 4; k++) acc[i][j][k] = 0.0f;

    issue(0, 0); CP_COMMIT();
    issue(1, 1); CP_COMMIT();

    const int crow = tid >> 2, cko = (tid & 3) * 8;  // convert: 8 floats/thread
    const int lrow = lane & 15, lk = (lane >> 4) * 8;
    for (int it = 0; it < 12; it++) {
        CP_WAIT1();
        __syncthreads();
        const uint32_t bufb = sb + (it & 1) * F_STAGE;
        const float* raw = (const float*)(smem + (it & 1) * F_STAGE);
        // convert raw fp32 -> fp16 A16 (apply interp weights on coarse chunks)
        {
            uint32_t hq[4];
            if (it < 4) {
                const float* r0 = raw + crow * 40 + cko;
                #pragma unroll
                for (int e = 0; e < 4; e++) hq[e] = pack2(r0[e*2], r0[e*2+1]);
            } else {
                float w0 = s_wt[crow * 3 + 0], w1v = s_wt[crow * 3 + 1], w2v = s_wt[crow * 3 + 2];
                const float* r0 = raw + crow * 40 + cko;
                const float* r1 = r0 + 5120;   // 20480 B / 4
                const float* r2 = r1 + 5120;
                #pragma unroll
                for (int e = 0; e < 4; e++) {
                    float x = w0 * r0[e*2]   + w1v * r1[e*2]   + w2v * r2[e*2];
                    float y = w0 * r0[e*2+1] + w1v * r1[e*2+1] + w2v * r2[e*2+1];
                    hq[e] = pack2(x, y);
                }
            }
            *(uint4*)(smem + F_CONV + crow * 80 + cko * 2) = make_uint4(hq[0], hq[1], hq[2], hq[3]);
        }
        __syncthreads();
        #pragma unroll
        for (int s = 0; s < 2; s++) {
            const int kc = s * 16;
            uint32_t fA[2][4];
            #pragma unroll
            for (int mf = 0; mf < 2; mf++) {
                uint32_t off = (uint32_t)(((wm * 32 + mf * 16 + lrow) * 40 + kc + lk) * 2);
                LDSM4(fA[mf][0], fA[mf][1], fA[mf][2], fA[mf][3], sb + F_CONV + off);
            }
            uint32_t fB[6][2];
            #pragma unroll
            for (int q = 0; q < 3; q++) {
                uint32_t off = (uint32_t)(((wn * 48 + q * 16 + lrow) * 40 + kc + lk) * 2);
                uint32_t r0, r1, r2, r3;
                LDSM4(r0, r1, r2, r3, bufb + F_SB + off);
                fB[q*2][0] = r0; fB[q*2][1] = r2;
                fB[q*2+1][0] = r1; fB[q*2+1][1] = r3;
            }
            #pragma unroll
            for (int mf = 0; mf < 2; mf++)
                #pragma unroll
                for (int nf = 0; nf < 6; nf++)
                    MMA16816(acc[mf][nf], fA[mf][0], fA[mf][1], fA[mf][2], fA[mf][3],
                             fB[nf][0], fB[nf][1]);
        }
        __syncthreads();
        if (it + 2 < 12) issue(it + 2, it & 1);
        CP_COMMIT();                 // empty group at drain keeps the count aligned
    }

    // epilogue: write C + GN1 partial stats from accumulators
    const int g = lane >> 2, tig = lane & 3;
    float gs[16];
    #pragma unroll
    for (int i = 0; i < 16; i++) gs[i] = 0.0f;
    #pragma unroll
    for (int mf = 0; mf < 2; mf++)
        #pragma unroll
        for (int nf = 0; nf < 6; nf++) {
            int row = m0 + wm * 32 + mf * 16 + g;
            int col = wn * 48 + nf * 8 + tig * 2;
            float d0 = acc[mf][nf][0], d1 = acc[mf][nf][1];
            float d2 = acc[mf][nf][2], d3 = acc[mf][nf][3];
            *(float2*)(C + (size_t)row * CMID + col)       = make_float2(d0, d1);
            *(float2*)(C + (size_t)(row + 8) * CMID + col) = make_float2(d2, d3);
            int grp = col / 24;
            gs[grp]     += d0 + d1 + d2 + d3;
            gs[8 + grp] += d0*d0 + d1*d1 + d2*d2 + d3*d3;
        }
    __syncthreads();
    float* red = (float*)smem;
    #pragma unroll
    for (int i = 0; i < 16; i++) red[i * 512 + tid] = gs[i];
    __syncthreads();
    for (int off = 256; off > 0; off >>= 1) {
        if (tid < off) {
            #pragma unroll
            for (int i = 0; i < 16; i++) red[i * 512 + tid] += red[i * 512 + tid + off];
        }
        __syncthreads();
    }
    if (tid < 16) {
        int cta = blockIdx.x & 127;
        int grp = tid & 7;
        part[(tid >= 8 ? 4096 : 0) + (bb * 8 + grp) * 128 + cta] = red[tid * 512];
    }
}

// ==================== GEMM2: single-term fp16, 512 thr, 3-stage cp.async ====================
#define G2_A32 0
#define G2_B   20480
#define G2_STAGE 30720
#define G2_CAH (3 * G2_STAGE)
#define G2_AFF (G2_CAH + 10240)
#define G2_SMEM (G2_AFF + 2 * CMID * 4)

__global__ void __launch_bounds__(512) gemm2_mma(
    const float* __restrict__ H, const __half* __restrict__ Bh,
    const float* __restrict__ a1, const float* __restrict__ b1,
    float* __restrict__ Out, float* __restrict__ part)
{
    extern __shared__ char smem[];
    const uint32_t sb = smem_u32(smem);
    const int tid = threadIdx.x, lane = tid & 31, wid = tid >> 5;
    const int wm = wid & 3, wn = wid >> 2;
    const int m0 = blockIdx.x * 128;
    const int bb = blockIdx.x >> 7;

    float* s_a = (float*)(smem + G2_AFF);
    float* s_b = s_a + CMID;
    for (int i = tid; i < CMID; i += 512) { s_a[i] = a1[bb * CMID + i]; s_b[i] = b1[bb * CMID + i]; }

    auto issue = [&](int it, int buf) {
        const int kc0 = it * 32;
        const uint32_t base = sb + buf * G2_STAGE;
        #pragma unroll
        for (int u = 0; u < 2; u++) {
            int i = u * 512 + tid;
            int row = i >> 3, ko = (i & 7) * 4;
            CP16(base + G2_A32 + row * 160 + ko * 4, H + (size_t)(m0 + row) * CMID + kc0 + ko);
        }
        {
            int row = tid >> 2, ko = (tid & 3) * 8;
            CP16(base + G2_B + row * 80 + ko * 2, Bh + (size_t)row * CMID + kc0 + ko);
        }
    };

    float acc[2][4][4];
    #pragma unroll
    for (int i = 0; i < 2; i++)
        #pragma unroll
        for (int j = 0; j < 4; j++)
            #pragma unroll
            for (int k = 0; k < 4; k++) acc[i][j][k] = 0.0f;

    __syncthreads();
    issue(0, 0); CP_COMMIT();
    issue(1, 1); CP_COMMIT();

    const int crow = tid >> 2, cko = (tid & 3) * 8;
    const int lrow = lane & 15, lk = (lane >> 4) * 8;
    for (int it = 0; it < 6; it++) {
        CP_WAIT1();
        __syncthreads();
        if (it + 2 < 6) issue(it + 2, (it + 2) % 3);
        CP_COMMIT();
        const uint32_t bufb = sb + (it % 3) * G2_STAGE;
        {
            const int kc0 = it * 32;
            const float* rowp = (const float*)(smem + (it % 3) * G2_STAGE + G2_A32) + crow * 40 + cko;
            uint32_t hq[4];
            #pragma unroll
            for (int e = 0; e < 4; e++) {
                int c = kc0 + cko + e * 2;
                float x = fmaxf(fmaf(rowp[e*2],   s_a[c],   s_b[c]),   0.0f);
                float y = fmaxf(fmaf(rowp[e*2+1], s_a[c+1], s_b[c+1]), 0.0f);
                hq[e] = pack2(x, y);
            }
            *(uint4*)(smem + G2_CAH + crow * 80 + cko * 2) = make_uint4(hq[0], hq[1], hq[2], hq[3]);
        }
        __syncthreads();
        #pragma unroll
        for (int s = 0; s < 2; s++) {
            const int kc = s * 16;
            uint32_t fA[2][4];
            #pragma unroll
            for (int mf = 0; mf < 2; mf++) {
                uint32_t off = (uint32_t)(((wm * 32 + mf * 16 + lrow) * 40 + kc + lk) * 2);
                LDSM4(fA[mf][0], fA[mf][1], fA[mf][2], fA[mf][3], sb + G2_CAH + off);
            }
            uint32_t fB[4][2];
            #pragma unroll
            for (int q = 0; q < 2; q++) {
                uint32_t off = (uint32_t)(((wn * 32 + q * 16 + lrow) * 40 + kc + lk) * 2);
                uint32_t r0, r1, r2, r3;
                LDSM4(r0, r1, r2, r3, bufb + G2_B + off);
                fB[q*2][0] = r0; fB[q*2][1] = r2;
                fB[q*2+1][0] = r1; fB[q*2+1][1] = r3;
            }
            #pragma unroll
            for (int mf = 0; mf < 2; mf++)
                #pragma unroll
                for (int nf = 0; nf < 4; nf++)
                    MMA16816(acc[mf][nf], fA[mf][0], fA[mf][1], fA[mf][2], fA[mf][3],
                             fB[nf][0], fB[nf][1]);
        }
        __syncthreads();
    }

    const int g = lane >> 2, tig = lane & 3;
    float gs[16];
    #pragma unroll
    for (int i = 0; i < 16; i++) gs[i] = 0.0f;
    #pragma unroll
    for (int mf = 0; mf < 2; mf++)
        #pragma unroll
        for (int nf = 0; nf < 4; nf++) {
            int row = m0 + wm * 32 + mf * 16 + g;
            int col = wn * 32 + nf * 8 + tig * 2;
            float d0 = acc[mf][nf][0], d1 = acc[mf][nf][1];
            float d2 = acc[mf][nf][2], d3 = acc[mf][nf][3];
            *(float2*)(Out + (size_t)row * COUT + col)       = make_float2(d0, d1);
            *(float2*)(Out + (size_t)(row + 8) * COUT + col) = make_float2(d2, d3);
            int grp = col >> 4;
            gs[grp]     += d0 + d1 + d2 + d3;
            gs[8 + grp] += d0*d0 + d1*d1 + d2*d2 + d3*d3;
        }
    __syncthreads();
    float* red = (float*)smem;
    #pragma unroll
    for (int i = 0; i < 16; i++) red[i * 512 + tid] = gs[i];
    __syncthreads();
    for (int off = 256; off > 0; off >>= 1) {
        if (tid < off) {
            #pragma unroll
            for (int i = 0; i < 16; i++) red[i * 512 + tid] += red[i * 512 + tid + off];
        }
        __syncthreads();
    }
    if (tid < 16) {
        int cta = blockIdx.x & 127;
        int grp = tid & 7;
        part[(tid >= 8 ? 4096 : 0) + (bb * 8 + grp) * 128 + cta] = red[tid * 512];
    }
}

// ==================== GN final ====================
template<int CPG>
__global__ void stats_final(
    const float* __restrict__ ps, const float* __restrict__ pss,
    const float* __restrict__ gamma, const float* __restrict__ beta,
    float* __restrict__ ac, float* __restrict__ bc, int Cdim)
{
    const int bg = blockIdx.x;
    const int b = bg >> 3, g = bg & 7;
    __shared__ float s_m, s_i;
    if (threadIdx.x == 0) {
        float s = 0.0f, ss = 0.0f;
        for (int i = 0; i < 128; i++) { s += ps[bg * 128 + i]; ss += pss[bg * 128 + i]; }
        float cnt = (float)NPTS * (float)CPG;
        float mu = s / cnt;
        float var = ss / cnt - mu * mu;
        s_m = mu; s_i = rsqrtf(var + EPS_GN);
    }
    __syncthreads();
    int ch = g * CPG + threadIdx.x;
    float a = gamma[ch] * s_i;
    ac[b * Cdim + ch] = a;
    bc[b * Cdim + ch] = beta[ch] - s_m * a;
}

// ==================== finalize: vectorized float4 ====================
__global__ void __launch_bounds__(256) finalize_kernel(
    float* __restrict__ out, const float* __restrict__ a, const float* __restrict__ bc)
{
    size_t i4 = (size_t)blockIdx.x * 256 + threadIdx.x;   // 2,097,152 float4s
    int c0 = (int)(i4 & 31) * 4;
    int b  = (int)(i4 >> 19);                              // 16384*128/4 = 2^19 per batch
    const float* ap = a  + b * COUT + c0;
    const float* bp = bc + b * COUT + c0;
    float4 v = ((float4*)out)[i4];
    v.x = fmaxf(fmaf(v.x, ap[0], bp[0]), 0.0f);
    v.y = fmaxf(fmaf(v.y, ap[1], bp[1]), 0.0f);
    v.z = fmaxf(fmaf(v.z, ap[2], bp[2]), 0.0f);
    v.w = fmaxf(fmaf(v.w, ap[3], bp[3]), 0.0f);
    ((float4*)out)[i4] = v;
}

// ==================== launch ====================
extern "C" void kernel_launch(void* const* d_in, const int* in_sizes, int n_in,
                              void* d_out, int out_size)
{
    const float* fine_xyz    = (const float*)d_in[0];
    const float* coarse_xyz  = (const float*)d_in[1];
    const float* fine_feat   = (const float*)d_in[2];
    const float* coarse_feat = (const float*)d_in[3];
    const float* w1          = (const float*)d_in[4];
    const float* g1_w        = (const float*)d_in[5];
    const float* g1_b        = (const float*)d_in[6];
    const float* w2          = (const float*)d_in[7];
    const float* g2_w        = (const float*)d_in[8];
    const float* g2_b        = (const float*)d_in[9];
    float* out = (float*)d_out;

    __half *w1h, *w2h;
    float *h1, *wt, *part1, *part2, *a1, *b1, *a2, *b2;
    int* idx;
    cudaGetSymbolAddress((void**)&h1, g_h1);
    cudaGetSymbolAddress((void**)&idx, g_idx);
    cudaGetSymbolAddress((void**)&wt, g_wt);
    cudaGetSymbolAddress((void**)&w1h, g_w1h);
    cudaGetSymbolAddress((void**)&w2h, g_w2h);
    cudaGetSymbolAddress((void**)&part1, g_part1);
    cudaGetSymbolAddress((void**)&part2, g_part2);
    cudaGetSymbolAddress((void**)&a1, g_a1);
    cudaGetSymbolAddress((void**)&b1, g_b1);
    cudaGetSymbolAddress((void**)&a2, g_a2);
    cudaGetSymbolAddress((void**)&b2, g_b2);

    cudaFuncSetAttribute(gemm1_fused, cudaFuncAttributeMaxDynamicSharedMemorySize, F_SMEM);
    cudaFuncSetAttribute(gemm2_mma, cudaFuncAttributeMaxDynamicSharedMemorySize, G2_SMEM);

    knn_kernel<<<dim3(NPTS / 128, BATCH), 128>>>(fine_xyz, coarse_xyz, idx, wt);
    prep_weights<<<(CMID * CIN + COUT * CMID + 255) / 256, 256>>>(w1, w2, w1h, w2h);
    gemm1_fused<<<BN_TOTAL / 128, 512, F_SMEM>>>(fine_feat, coarse_feat, idx, wt, w1h, h1, part1);
    stats_final<CMID / GROUPS><<<BATCH * GROUPS, CMID / GROUPS>>>(part1, part1 + 4096, g1_w, g1_b, a1, b1, CMID);
    gemm2_mma<<<BN_TOTAL / 128, 512, G2_SMEM>>>(h1, w2h, a1, b1, out, part2);
    stats_final<COUT / GROUPS><<<BATCH * GROUPS, COUT / GROUPS>>>(part2, part2 + 4096, g2_w, g2_b, a2, b2, COUT);
    finalize_kernel<<<(BN_TOTAL * COUT / 4) / 256, 256>>>(out, a2, b2);
}

// round 13
// speedup vs baseline: 1.5532x; 1.0191x over previous
#include <cuda_runtime.h>
#include <cuda_fp16.h>
#include <cstdint>
#include <cstddef>

// Problem constants
#define BATCH 4
#define NPTS  16384
#define SPTS  4096
#define CF    128
#define CC    256
#define CIN   384
#define CMID  192
#define COUT  128
#define GROUPS 8
#define EPS_GN 1e-5f
#define EPS_D  1e-8f
#define BN_TOTAL (BATCH * NPTS)   // 65536
#define CTAS_PER_BATCH 128

// -------------------- scratch (device globals; no allocation) --------------------
__device__ __align__(16) __half g_h1[(size_t)BN_TOTAL * CMID];   // 25 MB (pre-affine fp16)
__device__ int   g_idx[(size_t)BN_TOTAL * 3];
__device__ float g_wt[(size_t)BN_TOTAL * 3];
__device__ __align__(16) __half g_w1h[CMID * CIN];
__device__ __align__(16) __half g_w2h[COUT * CMID];
__device__ float g_part1[2 * 32 * CTAS_PER_BATCH];
__device__ float g_part2[2 * 32 * CTAS_PER_BATCH];
__device__ float g_a1[BATCH * CMID], g_b1[BATCH * CMID];
__device__ float g_a2[BATCH * COUT], g_b2[BATCH * COUT];

// ==================== helpers ====================
__device__ __forceinline__ uint32_t smem_u32(const void* p) {
    uint32_t a;
    asm("{ .reg .u64 t; cvta.to.shared.u64 t, %1; cvt.u32.u64 %0, t; }" : "=r"(a) : "l"(p));
    return a;
}
#define LDSM4(r0, r1, r2, r3, addr) \
    asm volatile("ldmatrix.sync.aligned.m8n8.x4.shared.b16 {%0,%1,%2,%3}, [%4];" \
        : "=r"(r0), "=r"(r1), "=r"(r2), "=r"(r3) : "r"(addr))
#define MMA16816(d, a0, a1, a2, a3, b0, b1) \
    asm volatile("mma.sync.aligned.m16n8k16.row.col.f32.f16.f16.f32 " \
        "{%0,%1,%2,%3},{%4,%5,%6,%7},{%8,%9},{%0,%1,%2,%3};" \
        : "+f"((d)[0]), "+f"((d)[1]), "+f"((d)[2]), "+f"((d)[3]) \
        : "r"(a0), "r"(a1), "r"(a2), "r"(a3), "r"(b0), "r"(b1))
#define CP16(dst, src) \
    asm volatile("cp.async.cg.shared.global [%0], [%1], 16;" :: "r"(dst), "l"(src))
#define CP_COMMIT() asm volatile("cp.async.commit_group;" ::: "memory")
#define CP_WAIT1()  asm volatile("cp.async.wait_group 1;" ::: "memory")

__device__ __forceinline__ uint32_t pack2(float x, float y) {
    __half hx = __float2half_rn(x), hy = __float2half_rn(y);
    return ((uint32_t)__half_as_ushort(hy) << 16) | __half_as_ushort(hx);
}

// ==================== Kernel 1: kNN (K=3) + IDW weights ====================
// candidates staged as (-2x, -2y, -2z, ||c||^2); paired screening with fminf
#define KNN_CHUNK 2048
__global__ void __launch_bounds__(128) knn_kernel(
    const float* __restrict__ fxyz, const float* __restrict__ cxyz,
    int* __restrict__ oidx, float* __restrict__ owt)
{
    __shared__ float4 cs[KNN_CHUNK];
    const int b = blockIdx.y;
    const int n = blockIdx.x * 128 + threadIdx.x;
    const float* fp = fxyz + ((size_t)b * NPTS + n) * 3;
    const float qx = fp[0], qy = fp[1], qz = fp[2];

    float s0 = 3.4e38f, s1 = 3.4e38f, s2 = 3.4e38f;
    int   i0 = 0, i1 = 0, i2 = 0;

    auto insert = [&](float sc, int iv) {
        if (sc < s1) {
            s2 = s1; i2 = i1;
            if (sc < s0) { s1 = s0; i1 = i0; s0 = sc; i0 = iv; }
            else         { s1 = sc; i1 = iv; }
        } else { s2 = sc; i2 = iv; }
    };

    for (int c0 = 0; c0 < SPTS; c0 += KNN_CHUNK) {
        __syncthreads();
        for (int j = threadIdx.x; j < KNN_CHUNK; j += 128) {
            const float* cp = cxyz + ((size_t)b * SPTS + c0 + j) * 3;
            float x = cp[0], y = cp[1], z = cp[2];
            cs[j] = make_float4(-2.0f * x, -2.0f * y, -2.0f * z, x*x + y*y + z*z);
        }
        __syncthreads();
        // score = ||c||^2 - 2 q.c (reference score minus the per-thread constant
        // ||q||^2: identical ordering). Candidates processed in ascending j.
        #pragma unroll 4
        for (int j = 0; j < KNN_CHUNK; j += 2) {
            float4 ca = cs[j], cb = cs[j + 1];
            float sa = fmaf(qx, ca.x, fmaf(qy, ca.y, fmaf(qz, ca.z, ca.w)));
            float sb2 = fmaf(qx, cb.x, fmaf(qy, cb.y, fmaf(qz, cb.z, cb.w)));
            if (fminf(sa, sb2) < s2) {
                if (sa  < s2) insert(sa,  c0 + j);
                if (sb2 < s2) insert(sb2, c0 + j + 1);
            }
        }
    }
    int ii[3] = { i0, i1, i2 };
    float w[3], wsum = 0.0f;
    #pragma unroll
    for (int k = 0; k < 3; k++) {
        const float* cp = cxyz + ((size_t)b * SPTS + ii[k]) * 3;
        float dx = qx - cp[0], dy = qy - cp[1], dz = qz - cp[2];
        float d2 = fmaxf(dx*dx + dy*dy + dz*dz, EPS_D);
        w[k] = 1.0f / d2; wsum += w[k];
    }
    float inv = 1.0f / wsum;
    size_t base = ((size_t)b * NPTS + n) * 3;
    #pragma unroll
    for (int k = 0; k < 3; k++) { oidx[base + k] = ii[k]; owt[base + k] = w[k] * inv; }
}

// ==================== Kernel 2: weights -> fp16 (hi only) ====================
__global__ void prep_weights(const float* __restrict__ w1, const float* __restrict__ w2,
                             __half* w1h, __half* w2h)
{
    int i = blockIdx.x * 256 + threadIdx.x;
    if (i < CMID * CIN) w1h[i] = __float2half_rn(w1[i]);
    int j = i - CMID * CIN;
    if (j >= 0 && j < COUT * CMID) w2h[j] = __float2half_rn(w2[j]);
}

// ==================== GEMM1 (fused interp): 512 thr, 2-stage cp.async + GN1 stats ====================
// h1(fp16)[65536,192] = concat(fine_feat, interp(coarse_feat)) @ w1^T
#define F_SA0 0
#define F_SA1 20480
#define F_SA2 40960
#define F_SB  61440
#define F_STAGE 76800
#define F_CONV (2 * F_STAGE)           // 153600: converted fp16 A (128x80)
#define F_IDX  (F_CONV + 10240)        // 163840
#define F_WT   (F_IDX + 1536)          // 165376
#define F_SMEM (F_WT + 1536)           // 166912

__global__ void __launch_bounds__(512) gemm1_fused(
    const float* __restrict__ ffeat, const float* __restrict__ cfeat,
    const int* __restrict__ idx, const float* __restrict__ wt,
    const __half* __restrict__ Bw,
    __half* __restrict__ C, float* __restrict__ part)
{
    extern __shared__ char smem[];
    const uint32_t sb = smem_u32(smem);
    const int tid = threadIdx.x, lane = tid & 31, wid = tid >> 5;
    const int wm = wid & 3, wn = wid >> 2;          // warp grid 4 x 4
    const int m0 = blockIdx.x * 128;
    const int bb = blockIdx.x >> 7;

    int*   s_idx = (int*)(smem + F_IDX);
    float* s_wt  = (float*)(smem + F_WT);
    if (tid < 384) {
        int row = tid / 3, k = tid - row * 3;
        s_idx[tid] = idx[((size_t)(m0 + row)) * 3 + k];
        s_wt[tid]  = wt[((size_t)(m0 + row)) * 3 + k];
    }
    __syncthreads();

    auto issue = [&](int it, int buf) {
        const uint32_t base = sb + buf * F_STAGE;
        if (it < 4) {
            const int kc0 = it * 32;
            #pragma unroll
            for (int u = 0; u < 2; u++) {
                int i = u * 512 + tid;
                int row = i >> 3, ch = i & 7;
                CP16(base + F_SA0 + row * 160 + ch * 16,
                     ffeat + (size_t)(m0 + row) * CF + kc0 + ch * 4);
            }
        } else {
            const int cc0 = it * 32 - 128;
            #pragma unroll
            for (int q = 0; q < 3; q++) {
                #pragma unroll
                for (int u = 0; u < 2; u++) {
                    int i = u * 512 + tid;
                    int row = i >> 3, ch = i & 7;
                    int j = s_idx[row * 3 + q];
                    CP16(base + F_SA0 + q * 20480 + row * 160 + ch * 16,
                         cfeat + ((size_t)bb * SPTS + j) * CC + cc0 + ch * 4);
                }
            }
        }
        {   // B: 768 CP16
            const int kc0 = it * 32;
            #pragma unroll
            for (int q = 0; q < 2; q++) {
                int i = q * 512 + tid;
                if (i < 768) {
                    int row = i >> 2, ko = (i & 3) * 8;
                    CP16(base + F_SB + row * 80 + ko * 2, Bw + (size_t)row * CIN + kc0 + ko);
                }
            }
        }
    };

    float acc[2][6][4];
    #pragma unroll
    for (int i = 0; i < 2; i++)
        #pragma unroll
        for (int j = 0; j < 6; j++)
            #pragma unroll
            for (int k = 0; k < 4; k++) acc[i][j][k] = 0.0f;

    issue(0, 0); CP_COMMIT();
    issue(1, 1); CP_COMMIT();

    const int crow = tid >> 2, cko = (tid & 3) * 8;
    const int lrow = lane & 15, lk = (lane >> 4) * 8;
    for (int it = 0; it < 12; it++) {
        CP_WAIT1();
        __syncthreads();
        const uint32_t bufb = sb + (it & 1) * F_STAGE;
        const float* raw = (const float*)(smem + (it & 1) * F_STAGE);
        {
            uint32_t hq[4];
            if (it < 4) {
                const float* r0 = raw + crow * 40 + cko;
                #pragma unroll
                for (int e = 0; e < 4; e++) hq[e] = pack2(r0[e*2], r0[e*2+1]);
            } else {
                float w0 = s_wt[crow * 3 + 0], w1v = s_wt[crow * 3 + 1], w2v = s_wt[crow * 3 + 2];
                const float* r0 = raw + crow * 40 + cko;
                const float* r1 = r0 + 5120;
                const float* r2 = r1 + 5120;
                #pragma unroll
                for (int e = 0; e < 4; e++) {
                    float x = w0 * r0[e*2]   + w1v * r1[e*2]   + w2v * r2[e*2];
                    float y = w0 * r0[e*2+1] + w1v * r1[e*2+1] + w2v * r2[e*2+1];
                    hq[e] = pack2(x, y);
                }
            }
            *(uint4*)(smem + F_CONV + crow * 80 + cko * 2) = make_uint4(hq[0], hq[1], hq[2], hq[3]);
        }
        __syncthreads();
        #pragma unroll
        for (int s = 0; s < 2; s++) {
            const int kc = s * 16;
            uint32_t fA[2][4];
            #pragma unroll
            for (int mf = 0; mf < 2; mf++) {
                uint32_t off = (uint32_t)(((wm * 32 + mf * 16 + lrow) * 40 + kc + lk) * 2);
                LDSM4(fA[mf][0], fA[mf][1], fA[mf][2], fA[mf][3], sb + F_CONV + off);
            }
            uint32_t fB[6][2];
            #pragma unroll
            for (int q = 0; q < 3; q++) {
                uint32_t off = (uint32_t)(((wn * 48 + q * 16 + lrow) * 40 + kc + lk) * 2);
                uint32_t r0, r1, r2, r3;
                LDSM4(r0, r1, r2, r3, bufb + F_SB + off);
                fB[q*2][0] = r0; fB[q*2][1] = r2;
                fB[q*2+1][0] = r1; fB[q*2+1][1] = r3;
            }
            #pragma unroll
            for (int mf = 0; mf < 2; mf++)
                #pragma unroll
                for (int nf = 0; nf < 6; nf++)
                    MMA16816(acc[mf][nf], fA[mf][0], fA[mf][1], fA[mf][2], fA[mf][3],
                             fB[nf][0], fB[nf][1]);
        }
        __syncthreads();
        if (it + 2 < 12) issue(it + 2, it & 1);
        CP_COMMIT();
    }

    // epilogue: write fp16 h1 + GN1 partial stats from fp32 accumulators
    const int g = lane >> 2, tig = lane & 3;
    float gs[16];
    #pragma unroll
    for (int i = 0; i < 16; i++) gs[i] = 0.0f;
    #pragma unroll
    for (int mf = 0; mf < 2; mf++)
        #pragma unroll
        for (int nf = 0; nf < 6; nf++) {
            int row = m0 + wm * 32 + mf * 16 + g;
            int col = wn * 48 + nf * 8 + tig * 2;
            float d0 = acc[mf][nf][0], d1 = acc[mf][nf][1];
            float d2 = acc[mf][nf][2], d3 = acc[mf][nf][3];
            *(uint32_t*)(C + (size_t)row * CMID + col)       = pack2(d0, d1);
            *(uint32_t*)(C + (size_t)(row + 8) * CMID + col) = pack2(d2, d3);
            int grp = col / 24;
            gs[grp]     += d0 + d1 + d2 + d3;
            gs[8 + grp] += d0*d0 + d1*d1 + d2*d2 + d3*d3;
        }
    __syncthreads();
    float* red = (float*)smem;
    #pragma unroll
    for (int i = 0; i < 16; i++) red[i * 512 + tid] = gs[i];
    __syncthreads();
    for (int off = 256; off > 0; off >>= 1) {
        if (tid < off) {
            #pragma unroll
            for (int i = 0; i < 16; i++) red[i * 512 + tid] += red[i * 512 + tid + off];
        }
        __syncthreads();
    }
    if (tid < 16) {
        int cta = blockIdx.x & 127;
        int grp = tid & 7;
        part[(tid >= 8 ? 4096 : 0) + (bb * 8 + grp) * 128 + cta] = red[tid * 512];
    }
}

// ==================== GEMM2: single-term fp16 (h1 fp16 in), 512 thr, 3-stage ====================
#define G2_A16 0
#define G2_B   10240
#define G2_STAGE 20480
#define G2_CAH (3 * G2_STAGE)            // 61440
#define G2_AFF (G2_CAH + 10240)          // 71680
#define G2_SMEM (G2_AFF + 2 * CMID * 4)  // 73216

__global__ void __launch_bounds__(512) gemm2_mma(
    const __half* __restrict__ H, const __half* __restrict__ Bh,
    const float* __restrict__ a1, const float* __restrict__ b1,
    float* __restrict__ Out, float* __restrict__ part)
{
    extern __shared__ char smem[];
    const uint32_t sb = smem_u32(smem);
    const int tid = threadIdx.x, lane = tid & 31, wid = tid >> 5;
    const int wm = wid & 3, wn = wid >> 2;
    const int m0 = blockIdx.x * 128;
    const int bb = blockIdx.x >> 7;

    float* s_a = (float*)(smem + G2_AFF);
    float* s_b = s_a + CMID;
    for (int i = tid; i < CMID; i += 512) { s_a[i] = a1[bb * CMID + i]; s_b[i] = b1[bb * CMID + i]; }

    auto issue = [&](int it, int buf) {
        const int kc0 = it * 32;
        const uint32_t base = sb + buf * G2_STAGE;
        {   // A16: 512 CP16 (128 rows x 4 groups of 8 halves)
            int row = tid >> 2, ko = (tid & 3) * 8;
            CP16(base + G2_A16 + row * 80 + ko * 2, H + (size_t)(m0 + row) * CMID + kc0 + ko);
        }
        {   // B: 512 CP16
            int row = tid >> 2, ko = (tid & 3) * 8;
            CP16(base + G2_B + row * 80 + ko * 2, Bh + (size_t)row * CMID + kc0 + ko);
        }
    };

    float acc[2][4][4];
    #pragma unroll
    for (int i = 0; i < 2; i++)
        #pragma unroll
        for (int j = 0; j < 4; j++)
            #pragma unroll
            for (int k = 0; k < 4; k++) acc[i][j][k] = 0.0f;

    __syncthreads();
    issue(0, 0); CP_COMMIT();
    issue(1, 1); CP_COMMIT();

    const int crow = tid >> 2, cko = (tid & 3) * 8;
    const int lrow = lane & 15, lk = (lane >> 4) * 8;
    for (int it = 0; it < 6; it++) {
        CP_WAIT1();
        __syncthreads();
        if (it + 2 < 6) issue(it + 2, (it + 2) % 3);
        CP_COMMIT();
        const uint32_t bufb = sb + (it % 3) * G2_STAGE;
        // convert: fp16 h1 + GN1 affine + relu -> fp16
        {
            const int kc0 = it * 32;
            uint4 rw = *(const uint4*)(smem + (it % 3) * G2_STAGE + G2_A16 + crow * 80 + cko * 2);
            uint32_t parts[4] = { rw.x, rw.y, rw.z, rw.w };
            uint32_t hq[4];
            #pragma unroll
            for (int e = 0; e < 4; e++) {
                __half2 hp = *reinterpret_cast<__half2*>(&parts[e]);
                int c = kc0 + cko + e * 2;
                float x = fmaxf(fmaf(__low2float(hp),  s_a[c],   s_b[c]),   0.0f);
                float y = fmaxf(fmaf(__high2float(hp), s_a[c+1], s_b[c+1]), 0.0f);
                hq[e] = pack2(x, y);
            }
            *(uint4*)(smem + G2_CAH + crow * 80 + cko * 2) = make_uint4(hq[0], hq[1], hq[2], hq[3]);
        }
        __syncthreads();
        #pragma unroll
        for (int s = 0; s < 2; s++) {
            const int kc = s * 16;
            uint32_t fA[2][4];
            #pragma unroll
            for (int mf = 0; mf < 2; mf++) {
                uint32_t off = (uint32_t)(((wm * 32 + mf * 16 + lrow) * 40 + kc + lk) * 2);
                LDSM4(fA[mf][0], fA[mf][1], fA[mf][2], fA[mf][3], sb + G2_CAH + off);
            }
            uint32_t fB[4][2];
            #pragma unroll
            for (int q = 0; q < 2; q++) {
                uint32_t off = (uint32_t)(((wn * 32 + q * 16 + lrow) * 40 + kc + lk) * 2);
                uint32_t r0, r1, r2, r3;
                LDSM4(r0, r1, r2, r3, bufb + G2_B + off);
                fB[q*2][0] = r0; fB[q*2][1] = r2;
                fB[q*2+1][0] = r1; fB[q*2+1][1] = r3;
            }
            #pragma unroll
            for (int mf = 0; mf < 2; mf++)
                #pragma unroll
                for (int nf = 0; nf < 4; nf++)
                    MMA16816(acc[mf][nf], fA[mf][0], fA[mf][1], fA[mf][2], fA[mf][3],
                             fB[nf][0], fB[nf][1]);
        }
        __syncthreads();
    }

    const int g = lane >> 2, tig = lane & 3;
    float gs[16];
    #pragma unroll
    for (int i = 0; i < 16; i++) gs[i] = 0.0f;
    #pragma unroll
    for (int mf = 0; mf < 2; mf++)
        #pragma unroll
        for (int nf = 0; nf < 4; nf++) {
            int row = m0 + wm * 32 + mf * 16 + g;
            int col = wn * 32 + nf * 8 + tig * 2;
            float d0 = acc[mf][nf][0], d1 = acc[mf][nf][1];
            float d2 = acc[mf][nf][2], d3 = acc[mf][nf][3];
            *(float2*)(Out + (size_t)row * COUT + col)       = make_float2(d0, d1);
            *(float2*)(Out + (size_t)(row + 8) * COUT + col) = make_float2(d2, d3);
            int grp = col >> 4;
            gs[grp]     += d0 + d1 + d2 + d3;
            gs[8 + grp] += d0*d0 + d1*d1 + d2*d2 + d3*d3;
        }
    __syncthreads();
    float* red = (float*)smem;
    #pragma unroll
    for (int i = 0; i < 16; i++) red[i * 512 + tid] = gs[i];
    __syncthreads();
    for (int off = 256; off > 0; off >>= 1) {
        if (tid < off) {
            #pragma unroll
            for (int i = 0; i < 16; i++) red[i * 512 + tid] += red[i * 512 + tid + off];
        }
        __syncthreads();
    }
    if (tid < 16) {
        int cta = blockIdx.x & 127;
        int grp = tid & 7;
        part[(tid >= 8 ? 4096 : 0) + (bb * 8 + grp) * 128 + cta] = red[tid * 512];
    }
}

// ==================== GN final: parallel 128-thread reduce ====================
template<int CPG>
__global__ void __launch_bounds__(128) stats_final(
    const float* __restrict__ ps, const float* __restrict__ pss,
    const float* __restrict__ gamma, const float* __restrict__ beta,
    float* __restrict__ ac, float* __restrict__ bc, int Cdim)
{
    const int bg = blockIdx.x;
    const int b = bg >> 3, g = bg & 7;
    const int tid = threadIdx.x, lane = tid & 31, wrp = tid >> 5;
    __shared__ float sh[8];
    __shared__ float s_m, s_i;

    float s = ps[bg * 128 + tid], ss = pss[bg * 128 + tid];
    #pragma unroll
    for (int off = 16; off > 0; off >>= 1) {
        s  += __shfl_down_sync(0xFFFFFFFF, s,  off);
        ss += __shfl_down_sync(0xFFFFFFFF, ss, off);
    }
    if (lane == 0) { sh[wrp] = s; sh[4 + wrp] = ss; }
    __syncthreads();
    if (tid == 0) {
        float ts  = sh[0] + sh[1] + sh[2] + sh[3];
        float tss = sh[4] + sh[5] + sh[6] + sh[7];
        float cnt = (float)NPTS * (float)CPG;
        float mu  = ts / cnt;
        float var = tss / cnt - mu * mu;
        s_m = mu; s_i = rsqrtf(var + EPS_GN);
    }
    __syncthreads();
    if (tid < CPG) {
        int ch = g * CPG + tid;
        float a = gamma[ch] * s_i;
        ac[b * Cdim + ch] = a;
        bc[b * Cdim + ch] = beta[ch] - s_m * a;
    }
}

// ==================== finalize: vectorized float4 ====================
__global__ void __launch_bounds__(256) finalize_kernel(
    float* __restrict__ out, const float* __restrict__ a, const float* __restrict__ bc)
{
    size_t i4 = (size_t)blockIdx.x * 256 + threadIdx.x;
    int c0 = (int)(i4 & 31) * 4;
    int b  = (int)(i4 >> 19);
    const float* ap = a  + b * COUT + c0;
    const float* bp = bc + b * COUT + c0;
    float4 v = ((float4*)out)[i4];
    v.x = fmaxf(fmaf(v.x, ap[0], bp[0]), 0.0f);
    v.y = fmaxf(fmaf(v.y, ap[1], bp[1]), 0.0f);
    v.z = fmaxf(fmaf(v.z, ap[2], bp[2]), 0.0f);
    v.w = fmaxf(fmaf(v.w, ap[3], bp[3]), 0.0f);
    ((float4*)out)[i4] = v;
}

// ==================== launch ====================
extern "C" void kernel_launch(void* const* d_in, const int* in_sizes, int n_in,
                              void* d_out, int out_size)
{
    const float* fine_xyz    = (const float*)d_in[0];
    const float* coarse_xyz  = (const float*)d_in[1];
    const float* fine_feat   = (const float*)d_in[2];
    const float* coarse_feat = (const float*)d_in[3];
    const float* w1          = (const float*)d_in[4];
    const float* g1_w        = (const float*)d_in[5];
    const float* g1_b        = (const float*)d_in[6];
    const float* w2          = (const float*)d_in[7];
    const float* g2_w        = (const float*)d_in[8];
    const float* g2_b        = (const float*)d_in[9];
    float* out = (float*)d_out;

    __half *h1, *w1h, *w2h;
    float *wt, *part1, *part2, *a1, *b1, *a2, *b2;
    int* idx;
    cudaGetSymbolAddress((void**)&h1, g_h1);
    cudaGetSymbolAddress((void**)&idx, g_idx);
    cudaGetSymbolAddress((void**)&wt, g_wt);
    cudaGetSymbolAddress((void**)&w1h, g_w1h);
    cudaGetSymbolAddress((void**)&w2h, g_w2h);
    cudaGetSymbolAddress((void**)&part1, g_part1);
    cudaGetSymbolAddress((void**)&part2, g_part2);
    cudaGetSymbolAddress((void**)&a1, g_a1);
    cudaGetSymbolAddress((void**)&b1, g_b1);
    cudaGetSymbolAddress((void**)&a2, g_a2);
    cudaGetSymbolAddress((void**)&b2, g_b2);

    cudaFuncSetAttribute(gemm1_fused, cudaFuncAttributeMaxDynamicSharedMemorySize, F_SMEM);
    cudaFuncSetAttribute(gemm2_mma, cudaFuncAttributeMaxDynamicSharedMemorySize, G2_SMEM);

    knn_kernel<<<dim3(NPTS / 128, BATCH), 128>>>(fine_xyz, coarse_xyz, idx, wt);
    prep_weights<<<(CMID * CIN + COUT * CMID + 255) / 256, 256>>>(w1, w2, w1h, w2h);
    gemm1_fused<<<BN_TOTAL / 128, 512, F_SMEM>>>(fine_feat, coarse_feat, idx, wt, w1h, h1, part1);
    stats_final<CMID / GROUPS><<<BATCH * GROUPS, 128>>>(part1, part1 + 4096, g1_w, g1_b, a1, b1, CMID);
    gemm2_mma<<<BN_TOTAL / 128, 512, G2_SMEM>>>(h1, w2h, a1, b1, out, part2);
    stats_final<COUT / GROUPS><<<BATCH * GROUPS, 128>>>(part2, part2 + 4096, g2_w, g2_b, a2, b2, COUT);
    finalize_kernel<<<(BN_TOTAL * COUT / 4) / 256, 256>>>(out, a2, b2);
}

// round 15
// speedup vs baseline: 1.7122x; 1.1024x over previous
#include <cuda_runtime.h>
#include <cuda_fp16.h>
#include <cstdint>
#include <cstddef>

// Problem constants
#define BATCH 4
#define NPTS  16384
#define SPTS  4096
#define CF    128
#define CC    256
#define CIN   384
#define CMID  192
#define COUT  128
#define GROUPS 8
#define EPS_GN 1e-5f
#define EPS_D  1e-8f
#define BN_TOTAL (BATCH * NPTS)   // 65536
#define CTAS_PER_BATCH 128

// -------------------- scratch (device globals; no allocation) --------------------
__device__ __align__(16) __half g_h1[(size_t)BN_TOTAL * CMID];        // 25 MB
__device__ __align__(16) __half g_P[(size_t)BATCH * SPTS * CMID];     // 6.3 MB
__device__ int   g_idx[(size_t)BN_TOTAL * 3];
__device__ float g_wt[(size_t)BN_TOTAL * 3];
__device__ __align__(16) __half g_w1h[CMID * CIN];
__device__ __align__(16) __half g_w2h[COUT * CMID];
__device__ float g_part1[2 * 32 * CTAS_PER_BATCH];
__device__ float g_part2[2 * 32 * CTAS_PER_BATCH];
__device__ float g_a1[BATCH * CMID], g_b1[BATCH * CMID];
__device__ float g_a2[BATCH * COUT], g_b2[BATCH * COUT];

// ==================== helpers ====================
__device__ __forceinline__ uint32_t smem_u32(const void* p) {
    uint32_t a;
    asm("{ .reg .u64 t; cvta.to.shared.u64 t, %1; cvt.u32.u64 %0, t; }" : "=r"(a) : "l"(p));
    return a;
}
#define LDSM4(r0, r1, r2, r3, addr) \
    asm volatile("ldmatrix.sync.aligned.m8n8.x4.shared.b16 {%0,%1,%2,%3}, [%4];" \
        : "=r"(r0), "=r"(r1), "=r"(r2), "=r"(r3) : "r"(addr))
#define MMA16816(d, a0, a1, a2, a3, b0, b1) \
    asm volatile("mma.sync.aligned.m16n8k16.row.col.f32.f16.f16.f32 " \
        "{%0,%1,%2,%3},{%4,%5,%6,%7},{%8,%9},{%0,%1,%2,%3};" \
        : "+f"((d)[0]), "+f"((d)[1]), "+f"((d)[2]), "+f"((d)[3]) \
        : "r"(a0), "r"(a1), "r"(a2), "r"(a3), "r"(b0), "r"(b1))
#define CP16(dst, src) \
    asm volatile("cp.async.cg.shared.global [%0], [%1], 16;" :: "r"(dst), "l"(src))
#define CP_COMMIT() asm volatile("cp.async.commit_group;" ::: "memory")
#define CP_WAIT1()  asm volatile("cp.async.wait_group 1;" ::: "memory")

__device__ __forceinline__ uint32_t pack2(float x, float y) {
    __half hx = __float2half_rn(x), hy = __float2half_rn(y);
    return ((uint32_t)__half_as_ushort(hy) << 16) | __half_as_ushort(hx);
}

// ==================== Kernel 1: kNN (K=3) + IDW weights ====================
#define KNN_CHUNK 2048
__global__ void __launch_bounds__(128) knn_kernel(
    const float* __restrict__ fxyz, const float* __restrict__ cxyz,
    int* __restrict__ oidx, float* __restrict__ owt)
{
    __shared__ float4 cs[KNN_CHUNK];
    const int b = blockIdx.y;
    const int n = blockIdx.x * 128 + threadIdx.x;
    const float* fp = fxyz + ((size_t)b * NPTS + n) * 3;
    const float qx = fp[0], qy = fp[1], qz = fp[2];

    float s0 = 3.4e38f, s1 = 3.4e38f, s2 = 3.4e38f;
    int   i0 = 0, i1 = 0, i2 = 0;

    auto insert = [&](float sc, int iv) {
        if (sc < s1) {
            s2 = s1; i2 = i1;
            if (sc < s0) { s1 = s0; i1 = i0; s0 = sc; i0 = iv; }
            else         { s1 = sc; i1 = iv; }
        } else { s2 = sc; i2 = iv; }
    };

    for (int c0 = 0; c0 < SPTS; c0 += KNN_CHUNK) {
        __syncthreads();
        for (int j = threadIdx.x; j < KNN_CHUNK; j += 128) {
            const float* cp = cxyz + ((size_t)b * SPTS + c0 + j) * 3;
            float x = cp[0], y = cp[1], z = cp[2];
            cs[j] = make_float4(-2.0f * x, -2.0f * y, -2.0f * z, x*x + y*y + z*z);
        }
        __syncthreads();
        // score = ||c||^2 - 2 q.c (reference score minus per-thread const ||q||^2)
        #pragma unroll 4
        for (int j = 0; j < KNN_CHUNK; j += 2) {
            float4 ca = cs[j], cb = cs[j + 1];
            float sa  = fmaf(qx, ca.x, fmaf(qy, ca.y, fmaf(qz, ca.z, ca.w)));
            float sb2 = fmaf(qx, cb.x, fmaf(qy, cb.y, fmaf(qz, cb.z, cb.w)));
            if (fminf(sa, sb2) < s2) {
                if (sa  < s2) insert(sa,  c0 + j);
                if (sb2 < s2) insert(sb2, c0 + j + 1);
            }
        }
    }
    int ii[3] = { i0, i1, i2 };
    float w[3], wsum = 0.0f;
    #pragma unroll
    for (int k = 0; k < 3; k++) {
        const float* cp = cxyz + ((size_t)b * SPTS + ii[k]) * 3;
        float dx = qx - cp[0], dy = qy - cp[1], dz = qz - cp[2];
        float d2 = fmaxf(dx*dx + dy*dy + dz*dz, EPS_D);
        w[k] = 1.0f / d2; wsum += w[k];
    }
    float inv = 1.0f / wsum;
    size_t base = ((size_t)b * NPTS + n) * 3;
    #pragma unroll
    for (int k = 0; k < 3; k++) { oidx[base + k] = ii[k]; owt[base + k] = w[k] * inv; }
}

// ==================== Kernel 2: weights -> fp16 ====================
__global__ void prep_weights(const float* __restrict__ w1, const float* __restrict__ w2,
                             __half* w1h, __half* w2h)
{
    int i = blockIdx.x * 256 + threadIdx.x;
    if (i < CMID * CIN) w1h[i] = __float2half_rn(w1[i]);
    int j = i - CMID * CIN;
    if (j >= 0 && j < COUT * CMID) w2h[j] = __float2half_rn(w2[j]);
}

// ==================== P-GEMM: P[b,s,:] = cfeat[b,s,:] @ W1coarse^T ====================
// per batch: M=4096, N=192, K=256. CTA 128x192, warp 4x4 (32x48), 3-stage.
#define P_A32 0
#define P_B   20480
#define P_STAGE 35840
#define P_CONV (3 * P_STAGE)            // 107520
#define P_SMEM (P_CONV + 10240)         // 117760

__global__ void __launch_bounds__(512) pgemm_mma(
    const float* __restrict__ cfeat, const __half* __restrict__ Bw,
    __half* __restrict__ P)
{
    extern __shared__ char smem[];
    const uint32_t sb = smem_u32(smem);
    const int tid = threadIdx.x, lane = tid & 31, wid = tid >> 5;
    const int wm = wid & 3, wn = wid >> 2;
    const int bb = blockIdx.x >> 5;
    const int m0 = (blockIdx.x & 31) * 128;

    auto issue = [&](int it, int buf) {
        const int kc0 = it * 32;
        const uint32_t base = sb + buf * P_STAGE;
        #pragma unroll
        for (int u = 0; u < 2; u++) {     // A32: 1024 CP16
            int i = u * 512 + tid;
            int row = i >> 3, ko = (i & 7) * 4;
            CP16(base + P_A32 + row * 160 + ko * 4,
                 cfeat + ((size_t)bb * SPTS + m0 + row) * CC + kc0 + ko);
        }
        #pragma unroll
        for (int q = 0; q < 2; q++) {     // B: 768 CP16 (w1h cols 128..383)
            int i = q * 512 + tid;
            if (i < 768) {
                int row = i >> 2, ko = (i & 3) * 8;
                CP16(base + P_B + row * 80 + ko * 2, Bw + (size_t)row * CIN + 128 + kc0 + ko);
            }
        }
    };

    float acc[2][6][4];
    #pragma unroll
    for (int i = 0; i < 2; i++)
        #pragma unroll
        for (int j = 0; j < 6; j++)
            #pragma unroll
            for (int k = 0; k < 4; k++) acc[i][j][k] = 0.0f;

    issue(0, 0); CP_COMMIT();
    issue(1, 1); CP_COMMIT();

    const int crow = tid >> 2, cko = (tid & 3) * 8;
    const int lrow = lane & 15, lk = (lane >> 4) * 8;
    for (int it = 0; it < 8; it++) {
        CP_WAIT1();
        __syncthreads();
        if (it + 2 < 8) issue(it + 2, (it + 2) % 3);   // 3-stage: safe before compute
        CP_COMMIT();
        const uint32_t bufb = sb + (it % 3) * P_STAGE;
        {   // convert fp32 -> fp16
            const float* rowp = (const float*)(smem + (it % 3) * P_STAGE + P_A32) + crow * 40 + cko;
            uint32_t hq[4];
            #pragma unroll
            for (int e = 0; e < 4; e++) hq[e] = pack2(rowp[e*2], rowp[e*2+1]);
            *(uint4*)(smem + P_CONV + crow * 80 + cko * 2) = make_uint4(hq[0], hq[1], hq[2], hq[3]);
        }
        __syncthreads();
        #pragma unroll
        for (int s = 0; s < 2; s++) {
            const int kc = s * 16;
            uint32_t fA[2][4];
            #pragma unroll
            for (int mf = 0; mf < 2; mf++) {
                uint32_t off = (uint32_t)(((wm * 32 + mf * 16 + lrow) * 40 + kc + lk) * 2);
                LDSM4(fA[mf][0], fA[mf][1], fA[mf][2], fA[mf][3], sb + P_CONV + off);
            }
            uint32_t fB[6][2];
            #pragma unroll
            for (int q = 0; q < 3; q++) {
                uint32_t off = (uint32_t)(((wn * 48 + q * 16 + lrow) * 40 + kc + lk) * 2);
                uint32_t r0, r1, r2, r3;
                LDSM4(r0, r1, r2, r3, bufb + P_B + off);
                fB[q*2][0] = r0; fB[q*2][1] = r2;
                fB[q*2+1][0] = r1; fB[q*2+1][1] = r3;
            }
            #pragma unroll
            for (int mf = 0; mf < 2; mf++)
                #pragma unroll
                for (int nf = 0; nf < 6; nf++)
                    MMA16816(acc[mf][nf], fA[mf][0], fA[mf][1], fA[mf][2], fA[mf][3],
                             fB[nf][0], fB[nf][1]);
        }
        __syncthreads();
    }

    const int g = lane >> 2, tig = lane & 3;
    #pragma unroll
    for (int mf = 0; mf < 2; mf++)
        #pragma unroll
        for (int nf = 0; nf < 6; nf++) {
            int row = m0 + wm * 32 + mf * 16 + g;
            int col = wn * 48 + nf * 8 + tig * 2;
            size_t base = ((size_t)bb * SPTS + row) * CMID + col;
            *(uint32_t*)(P + base)              = pack2(acc[mf][nf][0], acc[mf][nf][1]);
            *(uint32_t*)(P + base + 8 * CMID)   = pack2(acc[mf][nf][2], acc[mf][nf][3]);
        }
}

// ==================== GEMM1 (K=128 fine) + P-gather epilogue + GN1 stats ====================
// h1 = fine_feat @ W1fine^T + sum_k w_k * P[idx_k]
#define F_A32 0
#define F_B   20480
#define F_STAGE 35840                   // A32 20480 + B 15360
#define F_CONV (2 * F_STAGE)            // 71680 (10240)
#define F_PS   (F_CONV + 10240)         // 81920: PS fp32 128x192 = 98304
#define F_IDX  (F_PS + 98304)           // 180224 (1536)
#define F_WT   (F_IDX + 1536)           // 181760 (1536)
#define F_SMEM (F_WT + 1536)            // 183296

__global__ void __launch_bounds__(512) gemm1_mma(
    const float* __restrict__ ffeat, const __half* __restrict__ Pm,
    const int* __restrict__ idx, const float* __restrict__ wt,
    const __half* __restrict__ Bw,
    __half* __restrict__ C, float* __restrict__ part)
{
    extern __shared__ char smem[];
    const uint32_t sb = smem_u32(smem);
    const int tid = threadIdx.x, lane = tid & 31, wid = tid >> 5;
    const int wm = wid & 3, wn = wid >> 2;
    const int m0 = blockIdx.x * 128;
    const int bb = blockIdx.x >> 7;

    int*   s_idx = (int*)(smem + F_IDX);
    float* s_wt  = (float*)(smem + F_WT);
    if (tid < 384) {
        int row = tid / 3, k = tid - row * 3;
        s_idx[tid] = idx[((size_t)(m0 + row)) * 3 + k];
        s_wt[tid]  = wt[((size_t)(m0 + row)) * 3 + k];
    }

    auto issue = [&](int it, int buf) {
        const int kc0 = it * 32;
        const uint32_t base = sb + buf * F_STAGE;
        #pragma unroll
        for (int u = 0; u < 2; u++) {     // A32: 1024 CP16 (fine_feat)
            int i = u * 512 + tid;
            int row = i >> 3, ko = (i & 7) * 4;
            CP16(base + F_A32 + row * 160 + ko * 4,
                 ffeat + (size_t)(m0 + row) * CF + kc0 + ko);
        }
        #pragma unroll
        for (int q = 0; q < 2; q++) {     // B: 768 CP16 (w1h cols 0..127)
            int i = q * 512 + tid;
            if (i < 768) {
                int row = i >> 2, ko = (i & 3) * 8;
                CP16(base + F_B + row * 80 + ko * 2, Bw + (size_t)row * CIN + kc0 + ko);
            }
        }
    };

    float acc[2][6][4];
    #pragma unroll
    for (int i = 0; i < 2; i++)
        #pragma unroll
        for (int j = 0; j < 6; j++)
            #pragma unroll
            for (int k = 0; k < 4; k++) acc[i][j][k] = 0.0f;

    __syncthreads();     // s_idx/s_wt visible
    issue(0, 0); CP_COMMIT();
    issue(1, 1); CP_COMMIT();

    const int crow = tid >> 2, cko = (tid & 3) * 8;
    const int lrow = lane & 15, lk = (lane >> 4) * 8;
    for (int it = 0; it < 4; it++) {
        CP_WAIT1();
        __syncthreads();
        const uint32_t bufb = sb + (it & 1) * F_STAGE;
        {
            const float* rowp = (const float*)(smem + (it & 1) * F_STAGE + F_A32) + crow * 40 + cko;
            uint32_t hq[4];
            #pragma unroll
            for (int e = 0; e < 4; e++) hq[e] = pack2(rowp[e*2], rowp[e*2+1]);
            *(uint4*)(smem + F_CONV + crow * 80 + cko * 2) = make_uint4(hq[0], hq[1], hq[2], hq[3]);
        }
        __syncthreads();
        #pragma unroll
        for (int s = 0; s < 2; s++) {
            const int kc = s * 16;
            uint32_t fA[2][4];
            #pragma unroll
            for (int mf = 0; mf < 2; mf++) {
                uint32_t off = (uint32_t)(((wm * 32 + mf * 16 + lrow) * 40 + kc + lk) * 2);
                LDSM4(fA[mf][0], fA[mf][1], fA[mf][2], fA[mf][3], sb + F_CONV + off);
            }
            uint32_t fB[6][2];
            #pragma unroll
            for (int q = 0; q < 3; q++) {
                uint32_t off = (uint32_t)(((wn * 48 + q * 16 + lrow) * 40 + kc + lk) * 2);
                uint32_t r0, r1, r2, r3;
                LDSM4(r0, r1, r2, r3, bufb + F_B + off);
                fB[q*2][0] = r0; fB[q*2][1] = r2;
                fB[q*2+1][0] = r1; fB[q*2+1][1] = r3;
            }
            #pragma unroll
            for (int mf = 0; mf < 2; mf++)
                #pragma unroll
                for (int nf = 0; nf < 6; nf++)
                    MMA16816(acc[mf][nf], fA[mf][0], fA[mf][1], fA[mf][2], fA[mf][3],
                             fB[nf][0], fB[nf][1]);
        }
        __syncthreads();
        // 2-stage: prefetch ONLY after compute on buffer (it&1) is done (WAR safety)
        if (it + 2 < 4) issue(it + 2, it & 1);
        CP_COMMIT();                 // empty group at drain keeps the count aligned
    }

    // PS tile: PS[r][c] = sum_k w_k * P[idx_k(r)][c]  (fp32, smem)
    float* PS = (float*)(smem + F_PS);
    for (int i = tid; i < 128 * 24; i += 512) {     // 24 chunks of 8 cols per row
        int r = i / 24, cch = i - (i / 24) * 24;
        float w0 = s_wt[r * 3 + 0], w1v = s_wt[r * 3 + 1], w2v = s_wt[r * 3 + 2];
        const __half* P0 = Pm + ((size_t)bb * SPTS + s_idx[r * 3 + 0]) * CMID + cch * 8;
        const __half* P1 = Pm + ((size_t)bb * SPTS + s_idx[r * 3 + 1]) * CMID + cch * 8;
        const __half* P2 = Pm + ((size_t)bb * SPTS + s_idx[r * 3 + 2]) * CMID + cch * 8;
        uint4 u0 = *(const uint4*)P0, u1 = *(const uint4*)P1, u2 = *(const uint4*)P2;
        const __half2* h0 = (const __half2*)&u0;
        const __half2* h1p = (const __half2*)&u1;
        const __half2* h2 = (const __half2*)&u2;
        float* dst = PS + r * 192 + cch * 8;
        #pragma unroll
        for (int e = 0; e < 4; e++) {
            float2 f0 = __half22float2(h0[e]);
            float2 f1 = __half22float2(h1p[e]);
            float2 f2 = __half22float2(h2[e]);
            dst[e*2]   = w0 * f0.x + w1v * f1.x + w2v * f2.x;
            dst[e*2+1] = w0 * f0.y + w1v * f1.y + w2v * f2.y;
        }
    }
    __syncthreads();

    // epilogue: acc += PS; write fp16 h1 + GN1 partial stats
    const int g = lane >> 2, tig = lane & 3;
    float gs[16];
    #pragma unroll
    for (int i = 0; i < 16; i++) gs[i] = 0.0f;
    #pragma unroll
    for (int mf = 0; mf < 2; mf++)
        #pragma unroll
        for (int nf = 0; nf < 6; nf++) {
            int rl = wm * 32 + mf * 16 + g;
            int col = wn * 48 + nf * 8 + tig * 2;
            float d0 = acc[mf][nf][0] + PS[rl * 192 + col];
            float d1 = acc[mf][nf][1] + PS[rl * 192 + col + 1];
            float d2 = acc[mf][nf][2] + PS[(rl + 8) * 192 + col];
            float d3 = acc[mf][nf][3] + PS[(rl + 8) * 192 + col + 1];
            int row = m0 + rl;
            *(uint32_t*)(C + (size_t)row * CMID + col)       = pack2(d0, d1);
            *(uint32_t*)(C + (size_t)(row + 8) * CMID + col) = pack2(d2, d3);
            int grp = col / 24;
            gs[grp]     += d0 + d1 + d2 + d3;
            gs[8 + grp] += d0*d0 + d1*d1 + d2*d2 + d3*d3;
        }
    __syncthreads();
    float* red = (float*)smem;            // stage area is dead
    #pragma unroll
    for (int i = 0; i < 16; i++) red[i * 512 + tid] = gs[i];
    __syncthreads();
    for (int off = 256; off > 0; off >>= 1) {
        if (tid < off) {
            #pragma unroll
            for (int i = 0; i < 16; i++) red[i * 512 + tid] += red[i * 512 + tid + off];
        }
        __syncthreads();
    }
    if (tid < 16) {
        int cta = blockIdx.x & 127;
        int grp = tid & 7;
        part[(tid >= 8 ? 4096 : 0) + (bb * 8 + grp) * 128 + cta] = red[tid * 512];
    }
}

// ==================== GEMM2: single-term fp16 (h1 fp16 in), 512 thr, 3-stage ====================
#define G2_A16 0
#define G2_B   10240
#define G2_STAGE 20480
#define G2_CAH (3 * G2_STAGE)
#define G2_AFF (G2_CAH + 10240)
#define G2_SMEM (G2_AFF + 2 * CMID * 4)

__global__ void __launch_bounds__(512) gemm2_mma(
    const __half* __restrict__ H, const __half* __restrict__ Bh,
    const float* __restrict__ a1, const float* __restrict__ b1,
    float* __restrict__ Out, float* __restrict__ part)
{
    extern __shared__ char smem[];
    const uint32_t sb = smem_u32(smem);
    const int tid = threadIdx.x, lane = tid & 31, wid = tid >> 5;
    const int wm = wid & 3, wn = wid >> 2;
    const int m0 = blockIdx.x * 128;
    const int bb = blockIdx.x >> 7;

    float* s_a = (float*)(smem + G2_AFF);
    float* s_b = s_a + CMID;
    for (int i = tid; i < CMID; i += 512) { s_a[i] = a1[bb * CMID + i]; s_b[i] = b1[bb * CMID + i]; }

    auto issue = [&](int it, int buf) {
        const int kc0 = it * 32;
        const uint32_t base = sb + buf * G2_STAGE;
        {
            int row = tid >> 2, ko = (tid & 3) * 8;
            CP16(base + G2_A16 + row * 80 + ko * 2, H + (size_t)(m0 + row) * CMID + kc0 + ko);
        }
        {
            int row = tid >> 2, ko = (tid & 3) * 8;
            CP16(base + G2_B + row * 80 + ko * 2, Bh + (size_t)row * CMID + kc0 + ko);
        }
    };

    float acc[2][4][4];
    #pragma unroll
    for (int i = 0; i < 2; i++)
        #pragma unroll
        for (int j = 0; j < 4; j++)
            #pragma unroll
            for (int k = 0; k < 4; k++) acc[i][j][k] = 0.0f;

    __syncthreads();
    issue(0, 0); CP_COMMIT();
    issue(1, 1); CP_COMMIT();

    const int crow = tid >> 2, cko = (tid & 3) * 8;
    const int lrow = lane & 15, lk = (lane >> 4) * 8;
    for (int it = 0; it < 6; it++) {
        CP_WAIT1();
        __syncthreads();
        if (it + 2 < 6) issue(it + 2, (it + 2) % 3);   // 3-stage: safe
        CP_COMMIT();
        const uint32_t bufb = sb + (it % 3) * G2_STAGE;
        {
            const int kc0 = it * 32;
            uint4 rw = *(const uint4*)(smem + (it % 3) * G2_STAGE + G2_A16 + crow * 80 + cko * 2);
            uint32_t parts[4] = { rw.x, rw.y, rw.z, rw.w };
            uint32_t hq[4];
            #pragma unroll
            for (int e = 0; e < 4; e++) {
                __half2 hp = *reinterpret_cast<__half2*>(&parts[e]);
                int c = kc0 + cko + e * 2;
                float x = fmaxf(fmaf(__low2float(hp),  s_a[c],   s_b[c]),   0.0f);
                float y = fmaxf(fmaf(__high2float(hp), s_a[c+1], s_b[c+1]), 0.0f);
                hq[e] = pack2(x, y);
            }
            *(uint4*)(smem + G2_CAH + crow * 80 + cko * 2) = make_uint4(hq[0], hq[1], hq[2], hq[3]);
        }
        __syncthreads();
        #pragma unroll
        for (int s = 0; s < 2; s++) {
            const int kc = s * 16;
            uint32_t fA[2][4];
            #pragma unroll
            for (int mf = 0; mf < 2; mf++) {
                uint32_t off = (uint32_t)(((wm * 32 + mf * 16 + lrow) * 40 + kc + lk) * 2);
                LDSM4(fA[mf][0], fA[mf][1], fA[mf][2], fA[mf][3], sb + G2_CAH + off);
            }
            uint32_t fB[4][2];
            #pragma unroll
            for (int q = 0; q < 2; q++) {
                uint32_t off = (uint32_t)(((wn * 32 + q * 16 + lrow) * 40 + kc + lk) * 2);
                uint32_t r0, r1, r2, r3;
                LDSM4(r0, r1, r2, r3, bufb + G2_B + off);
                fB[q*2][0] = r0; fB[q*2][1] = r2;
                fB[q*2+1][0] = r1; fB[q*2+1][1] = r3;
            }
            #pragma unroll
            for (int mf = 0; mf < 2; mf++)
                #pragma unroll
                for (int nf = 0; nf < 4; nf++)
                    MMA16816(acc[mf][nf], fA[mf][0], fA[mf][1], fA[mf][2], fA[mf][3],
                             fB[nf][0], fB[nf][1]);
        }
        __syncthreads();
    }

    const int g = lane >> 2, tig = lane & 3;
    float gs[16];
    #pragma unroll
    for (int i = 0; i < 16; i++) gs[i] = 0.0f;
    #pragma unroll
    for (int mf = 0; mf < 2; mf++)
        #pragma unroll
        for (int nf = 0; nf < 4; nf++) {
            int row = m0 + wm * 32 + mf * 16 + g;
            int col = wn * 32 + nf * 8 + tig * 2;
            float d0 = acc[mf][nf][0], d1 = acc[mf][nf][1];
            float d2 = acc[mf][nf][2], d3 = acc[mf][nf][3];
            *(float2*)(Out + (size_t)row * COUT + col)       = make_float2(d0, d1);
            *(float2*)(Out + (size_t)(row + 8) * COUT + col) = make_float2(d2, d3);
            int grp = col >> 4;
            gs[grp]     += d0 + d1 + d2 + d3;
            gs[8 + grp] += d0*d0 + d1*d1 + d2*d2 + d3*d3;
        }
    __syncthreads();
    float* red = (float*)smem;
    #pragma unroll
    for (int i = 0; i < 16; i++) red[i * 512 + tid] = gs[i];
    __syncthreads();
    for (int off = 256; off > 0; off >>= 1) {
        if (tid < off) {
            #pragma unroll
            for (int i = 0; i < 16; i++) red[i * 512 + tid] += red[i * 512 + tid + off];
        }
        __syncthreads();
    }
    if (tid < 16) {
        int cta = blockIdx.x & 127;
        int grp = tid & 7;
        part[(tid >= 8 ? 4096 : 0) + (bb * 8 + grp) * 128 + cta] = red[tid * 512];
    }
}

// ==================== GN final: parallel 128-thread reduce ====================
template<int CPG>
__global__ void __launch_bounds__(128) stats_final(
    const float* __restrict__ ps, const float* __restrict__ pss,
    const float* __restrict__ gamma, const float* __restrict__ beta,
    float* __restrict__ ac, float* __restrict__ bc, int Cdim)
{
    const int bg = blockIdx.x;
    const int b = bg >> 3, g = bg & 7;
    const int tid = threadIdx.x, lane = tid & 31, wrp = tid >> 5;
    __shared__ float sh[8];
    __shared__ float s_m, s_i;

    float s = ps[bg * 128 + tid], ss = pss[bg * 128 + tid];
    #pragma unroll
    for (int off = 16; off > 0; off >>= 1) {
        s  += __shfl_down_sync(0xFFFFFFFF, s,  off);
        ss += __shfl_down_sync(0xFFFFFFFF, ss, off);
    }
    if (lane == 0) { sh[wrp] = s; sh[4 + wrp] = ss; }
    __syncthreads();
    if (tid == 0) {
        float ts  = sh[0] + sh[1] + sh[2] + sh[3];
        float tss = sh[4] + sh[5] + sh[6] + sh[7];
        float cnt = (float)NPTS * (float)CPG;
        float mu  = ts / cnt;
        float var = tss / cnt - mu * mu;
        s_m = mu; s_i = rsqrtf(var + EPS_GN);
    }
    __syncthreads();
    if (tid < CPG) {
        int ch = g * CPG + tid;
        float a = gamma[ch] * s_i;
        ac[b * Cdim + ch] = a;
        bc[b * Cdim + ch] = beta[ch] - s_m * a;
    }
}

// ==================== finalize: vectorized float4 ====================
__global__ void __launch_bounds__(256) finalize_kernel(
    float* __restrict__ out, const float* __restrict__ a, const float* __restrict__ bc)
{
    size_t i4 = (size_t)blockIdx.x * 256 + threadIdx.x;
    int c0 = (int)(i4 & 31) * 4;
    int b  = (int)(i4 >> 19);
    const float* ap = a  + b * COUT + c0;
    const float* bp = bc + b * COUT + c0;
    float4 v = ((float4*)out)[i4];
    v.x = fmaxf(fmaf(v.x, ap[0], bp[0]), 0.0f);
    v.y = fmaxf(fmaf(v.y, ap[1], bp[1]), 0.0f);
    v.z = fmaxf(fmaf(v.z, ap[2], bp[2]), 0.0f);
    v.w = fmaxf(fmaf(v.w, ap[3], bp[3]), 0.0f);
    ((float4*)out)[i4] = v;
}

// ==================== launch ====================
extern "C" void kernel_launch(void* const* d_in, const int* in_sizes, int n_in,
                              void* d_out, int out_size)
{
    const float* fine_xyz    = (const float*)d_in[0];
    const float* coarse_xyz  = (const float*)d_in[1];
    const float* fine_feat   = (const float*)d_in[2];
    const float* coarse_feat = (const float*)d_in[3];
    const float* w1          = (const float*)d_in[4];
    const float* g1_w        = (const float*)d_in[5];
    const float* g1_b        = (const float*)d_in[6];
    const float* w2          = (const float*)d_in[7];
    const float* g2_w        = (const float*)d_in[8];
    const float* g2_b        = (const float*)d_in[9];
    float* out = (float*)d_out;

    __half *h1, *Pm, *w1h, *w2h;
    float *wt, *part1, *part2, *a1, *b1, *a2, *b2;
    int* idx;
    cudaGetSymbolAddress((void**)&h1, g_h1);
    cudaGetSymbolAddress((void**)&Pm, g_P);
    cudaGetSymbolAddress((void**)&idx, g_idx);
    cudaGetSymbolAddress((void**)&wt, g_wt);
    cudaGetSymbolAddress((void**)&w1h, g_w1h);
    cudaGetSymbolAddress((void**)&w2h, g_w2h);
    cudaGetSymbolAddress((void**)&part1, g_part1);
    cudaGetSymbolAddress((void**)&part2, g_part2);
    cudaGetSymbolAddress((void**)&a1, g_a1);
    cudaGetSymbolAddress((void**)&b1, g_b1);
    cudaGetSymbolAddress((void**)&a2, g_a2);
    cudaGetSymbolAddress((void**)&b2, g_b2);

    cudaFuncSetAttribute(pgemm_mma, cudaFuncAttributeMaxDynamicSharedMemorySize, P_SMEM);
    cudaFuncSetAttribute(gemm1_mma, cudaFuncAttributeMaxDynamicSharedMemorySize, F_SMEM);
    cudaFuncSetAttribute(gemm2_mma, cudaFuncAttributeMaxDynamicSharedMemorySize, G2_SMEM);

    knn_kernel<<<dim3(NPTS / 128, BATCH), 128>>>(fine_xyz, coarse_xyz, idx, wt);
    prep_weights<<<(CMID * CIN + COUT * CMID + 255) / 256, 256>>>(w1, w2, w1h, w2h);
    pgemm_mma<<<BATCH * (SPTS / 128), 512, P_SMEM>>>(coarse_feat, w1h, Pm);
    gemm1_mma<<<BN_TOTAL / 128, 512, F_SMEM>>>(fine_feat, Pm, idx, wt, w1h, h1, part1);
    stats_final<CMID / GROUPS><<<BATCH * GROUPS, 128>>>(part1, part1 + 4096, g1_w, g1_b, a1, b1, CMID);
    gemm2_mma<<<BN_TOTAL / 128, 512, G2_SMEM>>>(h1, w2h, a1, b1, out, part2);
    stats_final<COUT / GROUPS><<<BATCH * GROUPS, 128>>>(part2, part2 + 4096, g2_w, g2_b, a2, b2, COUT);
    finalize_kernel<<<(BN_TOTAL * COUT / 4) / 256, 256>>>(out, a2, b2);
}